// round 1
// baseline (speedup 1.0000x reference)
#include <cuda_runtime.h>
#include <math.h>

// SwinTransformerBlockV2 fused kernel.
// Key fact: shift (8,8) is a multiple of window (4,4) => cyclic shift cancels
// and the attention mask is identically zero. So this is plain aligned 4x4
// window attention + post-norm residual MLP.
//
// Shapes: B=8, H=W=256, C=64, heads=4, head_dim=16, window N=16 tokens.
// Grid: 32768 windows / 4 per CTA = 8192 CTAs, 256 threads each.

#define NTHREADS 256
#define LD   68      // smem row stride for 64-wide rows (floats)
#define LDH  260     // smem row stride for 256-wide rows (floats)

// smem float offsets
#define OFF_X   0            // [64][68]  x tile
#define OFF_Q   4352         // [64][68]  q   (later: 'a' = proj out, then h2 = fc2 out)
#define OFF_K   8704         // [64][68]  k
#define OFF_V   13056        // [64][68]  v
#define OFF_W   17408        // [256][68] weight stage (also holds [64][260] for fc2)
#define OFF_X1  34816        // [64][68]  x + ln(attn)
#define OFF_H   39168        // [64][260] fc1+gelu output
#define OFF_ATT 39168        // [64][68]  attention output (inside H region, used before fc1)
#define OFF_KN  43520        // 16 tasks * [16][20] normalized-k scratch (inside H region)
#define SMEM_FLOATS 55808
#define SMEM_BYTES  (SMEM_FLOATS * 4)

__device__ float g_bias[4 * 256];   // [head][n*16+m]  16*sigmoid(cpb)
__device__ float g_scale[4];        // per-head logit scale

// ---------------------------------------------------------------------------
// Setup kernel: CPB MLP -> relative position bias table + logit scales
// ---------------------------------------------------------------------------
__device__ __forceinline__ float cpb_coord(int d) {
    float t = (8.0f / 3.0f) * (float)d;
    float v = log2f(fabsf(t) + 1.0f) / 3.0f;
    return (t < 0.0f) ? -v : v;
}

__global__ void bias_kernel(const float* __restrict__ w1, const float* __restrict__ b1,
                            const float* __restrict__ w2, const float* __restrict__ ls) {
    __shared__ float tab[49][4];
    int tid = threadIdx.x;
    for (int e = tid; e < 49 * 4; e += NTHREADS) {
        int q = e >> 2, h = e & 3;
        int a = q / 7, b = q % 7;
        float c0 = cpb_coord(a - 3);
        float c1 = cpb_coord(b - 3);
        float s = 0.0f;
        for (int j = 0; j < 512; j++) {
            float u = c0 * w1[2 * j] + c1 * w1[2 * j + 1] + b1[j];
            u = fmaxf(u, 0.0f);
            s += u * w2[h * 512 + j];
        }
        tab[q][h] = s;
    }
    __syncthreads();
    for (int e = tid; e < 4 * 256; e += NTHREADS) {
        int h = e >> 8;
        int n = (e >> 4) & 15;
        int m = e & 15;
        int idx = ((n >> 2) - (m >> 2) + 3) * 7 + ((n & 3) - (m & 3) + 3);
        float v = tab[idx][h];
        g_bias[h * 256 + n * 16 + m] = 16.0f / (1.0f + expf(-v));
    }
    if (tid < 4) g_scale[tid] = expf(fminf(ls[tid], logf(100.0f)));
}

// ---------------------------------------------------------------------------
// Helpers
// ---------------------------------------------------------------------------
__device__ __forceinline__ int token_gaddr(int blk, int lt) {
    int wi = blk * 4 + (lt >> 4);    // global window index
    int n  = lt & 15;                // token within window
    int b  = wi >> 12;               // image (4096 windows per image)
    int r  = wi & 4095;
    int wh = r >> 6, ww = r & 63;
    int row = wh * 4 + (n >> 2);
    int col = ww * 4 + (n & 3);
    return ((b * 256 + row) * 256 + col) * 64;
}

template <int R, int Kc, int LDD>
__device__ __forceinline__ void load_w(float* dst, const float* __restrict__ src, int tid) {
    constexpr int K4 = Kc >> 2;
    for (int idx = tid; idx < R * K4; idx += NTHREADS) {
        int r  = idx / K4;
        int c4 = idx - r * K4;
        *(float4*)(dst + r * LDD + c4 * 4) = *(const float4*)(src + r * Kc + c4 * 4);
    }
}

// acc[i][j] += A[rb+i][k] * B[cl+16j][k]  over k (both smem)
template <int TN, int K, int LDA, int LDB>
__device__ __forceinline__ void mm_tile(const float* __restrict__ A, const float* __restrict__ B,
                                        float (&acc)[4][TN], int rb, int cl) {
#pragma unroll 4
    for (int k0 = 0; k0 < K; k0 += 4) {
        float4 a[4];
#pragma unroll
        for (int i = 0; i < 4; i++) a[i] = *(const float4*)(A + (rb + i) * LDA + k0);
#pragma unroll
        for (int j = 0; j < TN; j++) {
            float4 b = *(const float4*)(B + (cl + 16 * j) * LDB + k0);
#pragma unroll
            for (int i = 0; i < 4; i++) {
                acc[i][j] = fmaf(a[i].x, b.x,
                            fmaf(a[i].y, b.y,
                            fmaf(a[i].z, b.z,
                            fmaf(a[i].w, b.w, acc[i][j]))));
            }
        }
    }
}

// ---------------------------------------------------------------------------
// Main fused kernel
// ---------------------------------------------------------------------------
__global__ __launch_bounds__(NTHREADS, 1)
void swin_kernel(const float* __restrict__ x,
                 const float* __restrict__ qkv_w, const float* __restrict__ qkv_b,
                 const float* __restrict__ proj_w, const float* __restrict__ proj_b,
                 const float* __restrict__ n1g, const float* __restrict__ n1b,
                 const float* __restrict__ n2g, const float* __restrict__ n2b,
                 const float* __restrict__ fc1_w, const float* __restrict__ fc1_b,
                 const float* __restrict__ fc2_w, const float* __restrict__ fc2_b,
                 float* __restrict__ out) {
    extern __shared__ float sm[];
    __shared__ float s_qkvb[192], s_projb[64], s_fc1b[256], s_fc2b[64];
    __shared__ float s_n1g[64], s_n1b[64], s_n2g[64], s_n2b[64];
    __shared__ float s_lnm[64], s_lnr[64], s_scale[4];

    const int tid = threadIdx.x;
    const int rg = tid >> 4, cl = tid & 15;
    const int rb = rg * 4;

    // ---- phase 0: biases / params + x tile + qkv weights ----
    if (tid < 192) s_qkvb[tid] = (tid >= 64 && tid < 128) ? 0.0f : qkv_b[tid];  // v2 zeroes k bias
    if (tid < 64) {
        s_projb[tid] = proj_b[tid];
        s_fc2b[tid]  = fc2_b[tid];
        s_n1g[tid] = n1g[tid]; s_n1b[tid] = n1b[tid];
        s_n2g[tid] = n2g[tid]; s_n2b[tid] = n2b[tid];
    }
    s_fc1b[tid] = fc1_b[tid];
    if (tid >= 192 && tid < 196) s_scale[tid - 192] = g_scale[tid - 192];

    {
        int lt = tid >> 2, pp = tid & 3;
        int gbase = token_gaddr(blockIdx.x, lt);
        const float4* xp = (const float4*)(x + gbase + pp * 16);
        float4* xd = (float4*)(sm + OFF_X + lt * LD + pp * 16);
#pragma unroll
        for (int i = 0; i < 4; i++) xd[i] = xp[i];
    }
    load_w<192, 64, LD>(sm + OFF_W, qkv_w, tid);
    __syncthreads();

    // ---- phase 1: qkv GEMM  [64,64] @ [64,192]^T ----
    {
        float acc[4][12];
#pragma unroll
        for (int i = 0; i < 4; i++)
#pragma unroll
            for (int j = 0; j < 12; j++) acc[i][j] = 0.0f;
        mm_tile<12, 64, LD, LD>(sm + OFF_X, sm + OFF_W, acc, rb, cl);
#pragma unroll
        for (int j = 0; j < 12; j++) {
            int c = cl + 16 * j;
            float bb = s_qkvb[c];
            int off, col;
            if (c < 64)       { off = OFF_Q; col = c; }
            else if (c < 128) { off = OFF_K; col = c - 64; }
            else              { off = OFF_V; col = c - 128; }
#pragma unroll
            for (int i = 0; i < 4; i++)
                sm[off + (rb + i) * LD + col] = acc[i][j] + bb;
        }
    }
    __syncthreads();

    // ---- phase 2: cosine attention (half-warp per (window, head)) ----
    {
        int warp = tid >> 5;
        int half = (tid >> 4) & 1;
        int task = warp * 2 + half;          // 0..15
        int wl = task >> 2, hh = task & 3;   // window-in-CTA, head
        int sl = tid & 15;                   // row within window
        int trow = wl * 16 + sl;
        float* kn = sm + OFF_KN + task * 320;  // [16][20]

        // normalized k row -> scratch
        float kv[16];
        {
            const float4* kp = (const float4*)(sm + OFF_K + trow * LD + hh * 16);
#pragma unroll
            for (int i = 0; i < 4; i++) {
                float4 t = kp[i];
                kv[4*i] = t.x; kv[4*i+1] = t.y; kv[4*i+2] = t.z; kv[4*i+3] = t.w;
            }
            float ss = 0.0f;
#pragma unroll
            for (int d = 0; d < 16; d++) ss += kv[d] * kv[d];
            float inv = 1.0f / fmaxf(sqrtf(ss), 1e-12f);
            float4* kd = (float4*)(kn + sl * 20);
#pragma unroll
            for (int i = 0; i < 4; i++) {
                float4 t;
                t.x = kv[4*i] * inv; t.y = kv[4*i+1] * inv;
                t.z = kv[4*i+2] * inv; t.w = kv[4*i+3] * inv;
                kd[i] = t;
            }
        }
        // normalized q row (scale folded in)
        float qv[16];
        {
            const float4* qp = (const float4*)(sm + OFF_Q + trow * LD + hh * 16);
#pragma unroll
            for (int i = 0; i < 4; i++) {
                float4 t = qp[i];
                qv[4*i] = t.x; qv[4*i+1] = t.y; qv[4*i+2] = t.z; qv[4*i+3] = t.w;
            }
            float ss = 0.0f;
#pragma unroll
            for (int d = 0; d < 16; d++) ss += qv[d] * qv[d];
            float inv = s_scale[hh] / fmaxf(sqrtf(ss), 1e-12f);
#pragma unroll
            for (int d = 0; d < 16; d++) qv[d] *= inv;
        }
        __syncwarp();

        // scores + bias
        float p[16];
        const float* bb = g_bias + hh * 256 + sl * 16;
#pragma unroll
        for (int c = 0; c < 16; c++) {
            const float4* kr = (const float4*)(kn + c * 20);
            float s = bb[c];
#pragma unroll
            for (int i = 0; i < 4; i++) {
                float4 t = kr[i];
                s = fmaf(qv[4*i], t.x, fmaf(qv[4*i+1], t.y,
                    fmaf(qv[4*i+2], t.z, fmaf(qv[4*i+3], t.w, s))));
            }
            p[c] = s;
        }
        // softmax over 16
        float mx = p[0];
#pragma unroll
        for (int c = 1; c < 16; c++) mx = fmaxf(mx, p[c]);
        float sum = 0.0f;
#pragma unroll
        for (int c = 0; c < 16; c++) { p[c] = expf(p[c] - mx); sum += p[c]; }
        float invs = 1.0f / sum;

        // O = P @ V
        float o[16];
#pragma unroll
        for (int d = 0; d < 16; d++) o[d] = 0.0f;
#pragma unroll
        for (int c = 0; c < 16; c++) {
            float pc = p[c] * invs;
            const float4* vp = (const float4*)(sm + OFF_V + (wl * 16 + c) * LD + hh * 16);
#pragma unroll
            for (int i = 0; i < 4; i++) {
                float4 t = vp[i];
                o[4*i]   = fmaf(pc, t.x, o[4*i]);
                o[4*i+1] = fmaf(pc, t.y, o[4*i+1]);
                o[4*i+2] = fmaf(pc, t.z, o[4*i+2]);
                o[4*i+3] = fmaf(pc, t.w, o[4*i+3]);
            }
        }
        float4* od = (float4*)(sm + OFF_ATT + trow * LD + hh * 16);
#pragma unroll
        for (int i = 0; i < 4; i++) {
            float4 t;
            t.x = o[4*i]; t.y = o[4*i+1]; t.z = o[4*i+2]; t.w = o[4*i+3];
            od[i] = t;
        }
    }
    __syncthreads();

    // ---- phase 3: proj GEMM ----
    load_w<64, 64, LD>(sm + OFF_W, proj_w, tid);
    __syncthreads();
    {
        float acc[4][4];
#pragma unroll
        for (int i = 0; i < 4; i++)
#pragma unroll
            for (int j = 0; j < 4; j++) acc[i][j] = 0.0f;
        mm_tile<4, 64, LD, LD>(sm + OFF_ATT, sm + OFF_W, acc, rb, cl);
#pragma unroll
        for (int j = 0; j < 4; j++) {
            int c = cl + 16 * j;
            float bb = s_projb[c];
#pragma unroll
            for (int i = 0; i < 4; i++)
                sm[OFF_Q + (rb + i) * LD + c] = acc[i][j] + bb;   // 'a'
        }
    }
    __syncthreads();

    // ---- phase 4: LN1 + residual -> x1 ----
    if (tid < 64) {
        const float* a = sm + OFF_Q + tid * LD;
        float mean = 0.0f;
#pragma unroll
        for (int c = 0; c < 64; c++) mean += a[c];
        mean *= (1.0f / 64.0f);
        float var = 0.0f;
#pragma unroll
        for (int c = 0; c < 64; c++) { float d = a[c] - mean; var += d * d; }
        var *= (1.0f / 64.0f);
        float rstd = rsqrtf(var + 1e-5f);
        float* x1 = sm + OFF_X1 + tid * LD;
        const float* xr = sm + OFF_X + tid * LD;
#pragma unroll
        for (int c = 0; c < 64; c++)
            x1[c] = xr[c] + (a[c] - mean) * rstd * s_n1g[c] + s_n1b[c];
    }
    __syncthreads();

    // ---- phase 5: fc1 + gelu ----
    load_w<256, 64, LD>(sm + OFF_W, fc1_w, tid);
    __syncthreads();
    {
        float acc[4][16];
#pragma unroll
        for (int i = 0; i < 4; i++)
#pragma unroll
            for (int j = 0; j < 16; j++) acc[i][j] = 0.0f;
        mm_tile<16, 64, LD, LD>(sm + OFF_X1, sm + OFF_W, acc, rb, cl);
#pragma unroll
        for (int j = 0; j < 16; j++) {
            int c = cl + 16 * j;
            float bb = s_fc1b[c];
#pragma unroll
            for (int i = 0; i < 4; i++) {
                float v = acc[i][j] + bb;
                v = v * 0.5f * (1.0f + erff(v * 0.70710678118654752f));
                sm[OFF_H + (rb + i) * LDH + c] = v;
            }
        }
    }
    __syncthreads();

    // ---- phase 6: fc2 ----
    load_w<64, 256, LDH>(sm + OFF_W, fc2_w, tid);
    __syncthreads();
    {
        float acc[4][4];
#pragma unroll
        for (int i = 0; i < 4; i++)
#pragma unroll
            for (int j = 0; j < 4; j++) acc[i][j] = 0.0f;
        mm_tile<4, 256, LDH, LDH>(sm + OFF_H, sm + OFF_W, acc, rb, cl);
#pragma unroll
        for (int j = 0; j < 4; j++) {
            int c = cl + 16 * j;
            float bb = s_fc2b[c];
#pragma unroll
            for (int i = 0; i < 4; i++)
                sm[OFF_Q + (rb + i) * LD + c] = acc[i][j] + bb;   // h2
        }
    }
    __syncthreads();

    // ---- phase 7: LN2 stats ----
    if (tid < 64) {
        const float* h2 = sm + OFF_Q + tid * LD;
        float mean = 0.0f;
#pragma unroll
        for (int c = 0; c < 64; c++) mean += h2[c];
        mean *= (1.0f / 64.0f);
        float var = 0.0f;
#pragma unroll
        for (int c = 0; c < 64; c++) { float d = h2[c] - mean; var += d * d; }
        var *= (1.0f / 64.0f);
        s_lnm[tid] = mean;
        s_lnr[tid] = rsqrtf(var + 1e-5f);
    }
    __syncthreads();

    // ---- phase 8: final residual + coalesced store ----
    {
        int t = tid >> 2, pp = tid & 3;
        int gbase = token_gaddr(blockIdx.x, t);
        float m = s_lnm[t], r = s_lnr[t];
#pragma unroll
        for (int q = 0; q < 4; q++) {
            int c = pp * 16 + q * 4;
            float4 xv = *(const float4*)(sm + OFF_X1 + t * LD + c);
            float4 hv = *(const float4*)(sm + OFF_Q + t * LD + c);
            float4 ov;
            ov.x = xv.x + (hv.x - m) * r * s_n2g[c]     + s_n2b[c];
            ov.y = xv.y + (hv.y - m) * r * s_n2g[c + 1] + s_n2b[c + 1];
            ov.z = xv.z + (hv.z - m) * r * s_n2g[c + 2] + s_n2b[c + 2];
            ov.w = xv.w + (hv.w - m) * r * s_n2g[c + 3] + s_n2b[c + 3];
            *(float4*)(out + gbase + c) = ov;
        }
    }
}

// ---------------------------------------------------------------------------
extern "C" void kernel_launch(void* const* d_in, const int* in_sizes, int n_in,
                              void* d_out, int out_size) {
    const float* x      = (const float*)d_in[0];
    const float* qkv_w  = (const float*)d_in[1];
    const float* qkv_b  = (const float*)d_in[2];
    const float* proj_w = (const float*)d_in[3];
    const float* proj_b = (const float*)d_in[4];
    const float* lscale = (const float*)d_in[5];
    const float* cpb_w1 = (const float*)d_in[6];
    const float* cpb_b1 = (const float*)d_in[7];
    const float* cpb_w2 = (const float*)d_in[8];
    const float* n1g    = (const float*)d_in[9];
    const float* n1b    = (const float*)d_in[10];
    const float* n2g    = (const float*)d_in[11];
    const float* n2b    = (const float*)d_in[12];
    const float* fc1_w  = (const float*)d_in[13];
    const float* fc1_b  = (const float*)d_in[14];
    const float* fc2_w  = (const float*)d_in[15];
    const float* fc2_b  = (const float*)d_in[16];
    float* out = (float*)d_out;

    cudaFuncSetAttribute(swin_kernel, cudaFuncAttributeMaxDynamicSharedMemorySize, SMEM_BYTES);

    bias_kernel<<<1, NTHREADS>>>(cpb_w1, cpb_b1, cpb_w2, lscale);
    swin_kernel<<<8192, NTHREADS, SMEM_BYTES>>>(x, qkv_w, qkv_b, proj_w, proj_b,
                                                n1g, n1b, n2g, n2b,
                                                fc1_w, fc1_b, fc2_w, fc2_b, out);
}

// round 3
// speedup vs baseline: 1.3226x; 1.3226x over previous
#include <cuda_runtime.h>
#include <math.h>

// SwinTransformerBlockV2 fused kernel, v2: 2 CTAs/SM.
// Shift (8,8) is a multiple of window (4,4) => cyclic shift cancels and the
// attention mask is identically zero: plain aligned 4x4 window attention.
//
// B=8, H=W=256, C=64, heads=4, head_dim=16, window N=16.
// Grid: 8192 CTAs x 256 threads, 4 windows (64 tokens) per CTA.
// Smem 104.4KB dynamic => 2 CTAs/SM; __launch_bounds__(256,2) caps regs at 128.

#define NTHREADS 256
#define LD   68      // row stride for 64-wide tiles (mod 32 == 4: conflict-free)
#define LDH2 132     // row stride for 128-wide tiles (mod 32 == 4)

// dynamic smem float offsets
#define OFF_X   0            // [64][68]  x tile; becomes x1 (in-place LN1 residual)
#define OFF_Q   4352         // [64][68]  q   (later: proj weights; part of H)
#define OFF_K   8704         // [64][68]  k   (normalized in place; later 'a'; part of H)
#define OFF_V   13056        // [64][68]  v   (later h2 = fc2 out)
#define OFF_W   17408        // [128][68] weight stage; also ATT [64][68]; fc2 slice [64][132]
#define OFF_H   OFF_Q        // [64][132] fc1+gelu half (spans Q+K regions: 8448 <= 8704)
#define SMEM_FLOATS 26112
#define SMEM_BYTES  (SMEM_FLOATS * 4)

__device__ float g_bias[4 * 256];   // [head][n*16+m]  16*sigmoid(cpb)
__device__ float g_scale[4];        // per-head logit scale

// ---------------------------------------------------------------------------
// Setup kernel: CPB MLP -> relative position bias table + logit scales
// ---------------------------------------------------------------------------
__device__ __forceinline__ float cpb_coord(int d) {
    float t = (8.0f / 3.0f) * (float)d;
    float v = log2f(fabsf(t) + 1.0f) / 3.0f;
    return (t < 0.0f) ? -v : v;
}

__global__ void bias_kernel(const float* __restrict__ w1, const float* __restrict__ b1,
                            const float* __restrict__ w2, const float* __restrict__ ls) {
    __shared__ float tab[49][4];
    int tid = threadIdx.x;
    for (int e = tid; e < 49 * 4; e += NTHREADS) {
        int q = e >> 2, h = e & 3;
        int a = q / 7, b = q % 7;
        float c0 = cpb_coord(a - 3);
        float c1 = cpb_coord(b - 3);
        float s = 0.0f;
        for (int j = 0; j < 512; j++) {
            float u = c0 * w1[2 * j] + c1 * w1[2 * j + 1] + b1[j];
            u = fmaxf(u, 0.0f);
            s += u * w2[h * 512 + j];
        }
        tab[q][h] = s;
    }
    __syncthreads();
    for (int e = tid; e < 4 * 256; e += NTHREADS) {
        int h = e >> 8;
        int n = (e >> 4) & 15;
        int m = e & 15;
        int idx = ((n >> 2) - (m >> 2) + 3) * 7 + ((n & 3) - (m & 3) + 3);
        float v = tab[idx][h];
        g_bias[h * 256 + n * 16 + m] = 16.0f / (1.0f + expf(-v));
    }
    if (tid < 4) g_scale[tid] = expf(fminf(ls[tid], logf(100.0f)));
}

// ---------------------------------------------------------------------------
// Helpers
// ---------------------------------------------------------------------------
__device__ __forceinline__ int token_gaddr(int blk, int lt) {
    int wi = blk * 4 + (lt >> 4);    // global window index
    int n  = lt & 15;                // token within window
    int b  = wi >> 12;               // image (4096 windows per image)
    int r  = wi & 4095;
    int wh = r >> 6, ww = r & 63;
    int row = wh * 4 + (n >> 2);
    int col = ww * 4 + (n & 3);
    return ((b * 256 + row) * 256 + col) * 64;
}

template <int R, int Kc, int LDD>
__device__ __forceinline__ void load_w(float* dst, const float* __restrict__ src, int tid) {
    constexpr int K4 = Kc >> 2;
    for (int idx = tid; idx < R * K4; idx += NTHREADS) {
        int r  = idx / K4;
        int c4 = idx - r * K4;
        *(float4*)(dst + r * LDD + c4 * 4) = *(const float4*)(src + r * Kc + c4 * 4);
    }
}

// fc2 column-slice loader: dst[r][c] = src[r*256 + h0 + c], r<64, c<128
__device__ __forceinline__ void load_w_slice(float* dst, const float* __restrict__ src,
                                             int h0, int tid) {
    for (int idx = tid; idx < 64 * 32; idx += NTHREADS) {
        int r  = idx >> 5;
        int c4 = idx & 31;
        *(float4*)(dst + r * LDH2 + c4 * 4) = *(const float4*)(src + r * 256 + h0 + c4 * 4);
    }
}

// acc[i][j] += A[rb+i][k] * B[cl+16j][k]  over k (both smem)
template <int TN, int K, int LDA, int LDB>
__device__ __forceinline__ void mm_tile(const float* __restrict__ A, const float* __restrict__ B,
                                        float (&acc)[4][TN], int rb, int cl) {
#pragma unroll 4
    for (int k0 = 0; k0 < K; k0 += 4) {
        float4 a[4];
#pragma unroll
        for (int i = 0; i < 4; i++) a[i] = *(const float4*)(A + (rb + i) * LDA + k0);
#pragma unroll
        for (int j = 0; j < TN; j++) {
            float4 b = *(const float4*)(B + (cl + 16 * j) * LDB + k0);
#pragma unroll
            for (int i = 0; i < 4; i++) {
                acc[i][j] = fmaf(a[i].x, b.x,
                            fmaf(a[i].y, b.y,
                            fmaf(a[i].z, b.z,
                            fmaf(a[i].w, b.w, acc[i][j]))));
            }
        }
    }
}

// ---------------------------------------------------------------------------
// Main fused kernel
// ---------------------------------------------------------------------------
__global__ __launch_bounds__(NTHREADS, 2)
void swin_kernel(const float* __restrict__ x,
                 const float* __restrict__ qkv_w, const float* __restrict__ qkv_b,
                 const float* __restrict__ proj_w, const float* __restrict__ proj_b,
                 const float* __restrict__ n1g, const float* __restrict__ n1b,
                 const float* __restrict__ n2g, const float* __restrict__ n2b,
                 const float* __restrict__ fc1_w, const float* __restrict__ fc1_b,
                 const float* __restrict__ fc2_w, const float* __restrict__ fc2_b,
                 float* __restrict__ out) {
    extern __shared__ float sm[];
    __shared__ float s_qkvb[192], s_projb[64], s_fc1b[256], s_fc2b[64];
    __shared__ float s_n1g[64], s_n1b[64], s_n2g[64], s_n2b[64];
    __shared__ float s_lnm[64], s_lnr[64], s_scale[4];

    const int tid = threadIdx.x;
    const int rg = tid >> 4, cl = tid & 15;
    const int rb = rg * 4;

    // ---- phase 0: params + x tile + q/k weight stage (rows 0..127) ----
    if (tid < 192) s_qkvb[tid] = (tid >= 64 && tid < 128) ? 0.0f : qkv_b[tid];  // v2 zeroes k bias
    if (tid < 64) {
        s_projb[tid] = proj_b[tid];
        s_fc2b[tid]  = fc2_b[tid];
        s_n1g[tid] = n1g[tid]; s_n1b[tid] = n1b[tid];
        s_n2g[tid] = n2g[tid]; s_n2b[tid] = n2b[tid];
    }
    s_fc1b[tid] = fc1_b[tid];
    if (tid >= 192 && tid < 196) s_scale[tid - 192] = g_scale[tid - 192];

    {
        int lt = tid >> 2, pp = tid & 3;
        int gbase = token_gaddr(blockIdx.x, lt);
        const float4* xp = (const float4*)(x + gbase + pp * 16);
        float4* xd = (float4*)(sm + OFF_X + lt * LD + pp * 16);
#pragma unroll
        for (int i = 0; i < 4; i++) xd[i] = xp[i];
    }
    load_w<128, 64, LD>(sm + OFF_W, qkv_w, tid);
    __syncthreads();

    // ---- phase 1: Q,K GEMM  [64,64] @ [64,128]^T ----
    {
        float acc[4][8];
#pragma unroll
        for (int i = 0; i < 4; i++)
#pragma unroll
            for (int j = 0; j < 8; j++) acc[i][j] = 0.0f;
        mm_tile<8, 64, LD, LD>(sm + OFF_X, sm + OFF_W, acc, rb, cl);
#pragma unroll
        for (int j = 0; j < 8; j++) {
            int c = cl + 16 * j;
            float bb = s_qkvb[c];
            int off = (c < 64) ? OFF_Q : (OFF_K - 64);
#pragma unroll
            for (int i = 0; i < 4; i++)
                sm[off + (rb + i) * LD + c] = acc[i][j] + bb;
        }
    }
    __syncthreads();

    // ---- phase 2: V weights + V GEMM ----
    load_w<64, 64, LD>(sm + OFF_W, qkv_w + 128 * 64, tid);
    __syncthreads();
    {
        float acc[4][4];
#pragma unroll
        for (int i = 0; i < 4; i++)
#pragma unroll
            for (int j = 0; j < 4; j++) acc[i][j] = 0.0f;
        mm_tile<4, 64, LD, LD>(sm + OFF_X, sm + OFF_W, acc, rb, cl);
#pragma unroll
        for (int j = 0; j < 4; j++) {
            int c = cl + 16 * j;
            float bb = s_qkvb[128 + c];
#pragma unroll
            for (int i = 0; i < 4; i++)
                sm[OFF_V + (rb + i) * LD + c] = acc[i][j] + bb;
        }
    }
    __syncthreads();

    // ---- phase 3: cosine attention (half-warp per (window, head)) ----
    {
        int warp = tid >> 5;
        int half = (tid >> 4) & 1;
        int task = warp * 2 + half;          // 0..15
        int wl = task >> 2, hh = task & 3;   // window-in-CTA, head
        int sl = tid & 15;                   // row within window
        int trow = wl * 16 + sl;

        // normalized q row (scale folded in) -> regs
        float qv[16];
        {
            const float4* qp = (const float4*)(sm + OFF_Q + trow * LD + hh * 16);
#pragma unroll
            for (int i = 0; i < 4; i++) {
                float4 t = qp[i];
                qv[4*i] = t.x; qv[4*i+1] = t.y; qv[4*i+2] = t.z; qv[4*i+3] = t.w;
            }
            float ss = 0.0f;
#pragma unroll
            for (int d = 0; d < 16; d++) ss += qv[d] * qv[d];
            float inv = s_scale[hh] * rsqrtf(fmaxf(ss, 1e-24f));
#pragma unroll
            for (int d = 0; d < 16; d++) qv[d] *= inv;
        }
        // normalize k row IN PLACE
        {
            float4* kp = (float4*)(sm + OFF_K + trow * LD + hh * 16);
            float kv[16];
#pragma unroll
            for (int i = 0; i < 4; i++) {
                float4 t = kp[i];
                kv[4*i] = t.x; kv[4*i+1] = t.y; kv[4*i+2] = t.z; kv[4*i+3] = t.w;
            }
            float ss = 0.0f;
#pragma unroll
            for (int d = 0; d < 16; d++) ss += kv[d] * kv[d];
            float inv = rsqrtf(fmaxf(ss, 1e-24f));
#pragma unroll
            for (int i = 0; i < 4; i++) {
                float4 t;
                t.x = kv[4*i] * inv; t.y = kv[4*i+1] * inv;
                t.z = kv[4*i+2] * inv; t.w = kv[4*i+3] * inv;
                kp[i] = t;
            }
        }
        __syncwarp();

        // scores + bias
        float p[16];
        const float* bb = g_bias + hh * 256 + sl * 16;
#pragma unroll
        for (int c = 0; c < 16; c++) {
            const float4* kr = (const float4*)(sm + OFF_K + (wl * 16 + c) * LD + hh * 16);
            float s = bb[c];
#pragma unroll
            for (int i = 0; i < 4; i++) {
                float4 t = kr[i];
                s = fmaf(qv[4*i], t.x, fmaf(qv[4*i+1], t.y,
                    fmaf(qv[4*i+2], t.z, fmaf(qv[4*i+3], t.w, s))));
            }
            p[c] = s;
        }
        // softmax over 16
        float mx = p[0];
#pragma unroll
        for (int c = 1; c < 16; c++) mx = fmaxf(mx, p[c]);
        float sum = 0.0f;
#pragma unroll
        for (int c = 0; c < 16; c++) { p[c] = __expf(p[c] - mx); sum += p[c]; }
        float invs = 1.0f / sum;

        // O = P @ V  -> write to W region (free)
        float o[16];
#pragma unroll
        for (int d = 0; d < 16; d++) o[d] = 0.0f;
#pragma unroll
        for (int c = 0; c < 16; c++) {
            float pc = p[c] * invs;
            const float4* vp = (const float4*)(sm + OFF_V + (wl * 16 + c) * LD + hh * 16);
#pragma unroll
            for (int i = 0; i < 4; i++) {
                float4 t = vp[i];
                o[4*i]   = fmaf(pc, t.x, o[4*i]);
                o[4*i+1] = fmaf(pc, t.y, o[4*i+1]);
                o[4*i+2] = fmaf(pc, t.z, o[4*i+2]);
                o[4*i+3] = fmaf(pc, t.w, o[4*i+3]);
            }
        }
        float4* od = (float4*)(sm + OFF_W + trow * LD + hh * 16);
#pragma unroll
        for (int i = 0; i < 4; i++) {
            float4 t;
            t.x = o[4*i]; t.y = o[4*i+1]; t.z = o[4*i+2]; t.w = o[4*i+3];
            od[i] = t;
        }
    }
    __syncthreads();

    // ---- phase 4: proj GEMM (ATT in W region, weights into dead Q buffer) ----
    load_w<64, 64, LD>(sm + OFF_Q, proj_w, tid);
    __syncthreads();
    {
        float acc[4][4];
#pragma unroll
        for (int i = 0; i < 4; i++)
#pragma unroll
            for (int j = 0; j < 4; j++) acc[i][j] = 0.0f;
        mm_tile<4, 64, LD, LD>(sm + OFF_W, sm + OFF_Q, acc, rb, cl);
        __syncthreads();   // ensure K (normalized k) reads done before 'a' overwrites... (K dead; guard Q restage below)
#pragma unroll
        for (int j = 0; j < 4; j++) {
            int c = cl + 16 * j;
            float bb = s_projb[c];
#pragma unroll
            for (int i = 0; i < 4; i++)
                sm[OFF_K + (rb + i) * LD + c] = acc[i][j] + bb;   // 'a' into dead K buffer
        }
    }
    __syncthreads();

    // ---- phase 5: LN1 + residual IN PLACE over x ----
    if (tid < 64) {
        const float* a = sm + OFF_K + tid * LD;
        float mean = 0.0f;
#pragma unroll
        for (int c = 0; c < 64; c++) mean += a[c];
        mean *= (1.0f / 64.0f);
        float var = 0.0f;
#pragma unroll
        for (int c = 0; c < 64; c++) { float d = a[c] - mean; var += d * d; }
        var *= (1.0f / 64.0f);
        float rstd = rsqrtf(var + 1e-5f);
        float* xr = sm + OFF_X + tid * LD;
#pragma unroll
        for (int c = 0; c < 64; c++)
            xr[c] = xr[c] + (a[c] - mean) * rstd * s_n1g[c] + s_n1b[c];
    }
    __syncthreads();

    // ---- phase 6: MLP in two 128-wide halves, fc2 acc in registers ----
    float acc2[4][4];
#pragma unroll
    for (int i = 0; i < 4; i++)
#pragma unroll
        for (int j = 0; j < 4; j++) acc2[i][j] = 0.0f;

#pragma unroll 1
    for (int h = 0; h < 2; h++) {
        // fc1 weight half
        load_w<128, 64, LD>(sm + OFF_W, fc1_w + h * 128 * 64, tid);
        __syncthreads();
        // fc1 half GEMM + gelu -> H region [64][132]
        {
            float acc[4][8];
#pragma unroll
            for (int i = 0; i < 4; i++)
#pragma unroll
                for (int j = 0; j < 8; j++) acc[i][j] = 0.0f;
            mm_tile<8, 64, LD, LD>(sm + OFF_X, sm + OFF_W, acc, rb, cl);
            __syncthreads();   // H overlays old Q/K data; all reads of those are done
#pragma unroll
            for (int j = 0; j < 8; j++) {
                int c = cl + 16 * j;
                float bb = s_fc1b[h * 128 + c];
#pragma unroll
                for (int i = 0; i < 4; i++) {
                    float v = acc[i][j] + bb;
                    v = v * 0.5f * (1.0f + erff(v * 0.70710678118654752f));
                    sm[OFF_H + (rb + i) * LDH2 + c] = v;
                }
            }
        }
        __syncthreads();
        // fc2 column slice -> W region
        load_w_slice(sm + OFF_W, fc2_w, h * 128, tid);
        __syncthreads();
        // accumulate fc2 partial
        mm_tile<4, 128, LDH2, LDH2>(sm + OFF_H, sm + OFF_W, acc2, rb, cl);
        __syncthreads();
    }

    // h2 -> dead V buffer
#pragma unroll
    for (int j = 0; j < 4; j++) {
        int c = cl + 16 * j;
        float bb = s_fc2b[c];
#pragma unroll
        for (int i = 0; i < 4; i++)
            sm[OFF_V + (rb + i) * LD + c] = acc2[i][j] + bb;
    }
    __syncthreads();

    // ---- phase 7: LN2 stats ----
    if (tid < 64) {
        const float* h2 = sm + OFF_V + tid * LD;
        float mean = 0.0f;
#pragma unroll
        for (int c = 0; c < 64; c++) mean += h2[c];
        mean *= (1.0f / 64.0f);
        float var = 0.0f;
#pragma unroll
        for (int c = 0; c < 64; c++) { float d = h2[c] - mean; var += d * d; }
        var *= (1.0f / 64.0f);
        s_lnm[tid] = mean;
        s_lnr[tid] = rsqrtf(var + 1e-5f);
    }
    __syncthreads();

    // ---- phase 8: final residual + coalesced store ----
    {
        int t = tid >> 2, pp = tid & 3;
        int gbase = token_gaddr(blockIdx.x, t);
        float m = s_lnm[t], r = s_lnr[t];
#pragma unroll
        for (int q = 0; q < 4; q++) {
            int c = pp * 16 + q * 4;
            float4 xv = *(const float4*)(sm + OFF_X + t * LD + c);
            float4 hv = *(const float4*)(sm + OFF_V + t * LD + c);
            float4 ov;
            ov.x = xv.x + (hv.x - m) * r * s_n2g[c]     + s_n2b[c];
            ov.y = xv.y + (hv.y - m) * r * s_n2g[c + 1] + s_n2b[c + 1];
            ov.z = xv.z + (hv.z - m) * r * s_n2g[c + 2] + s_n2b[c + 2];
            ov.w = xv.w + (hv.w - m) * r * s_n2g[c + 3] + s_n2b[c + 3];
            *(float4*)(out + gbase + c) = ov;
        }
    }
}

// ---------------------------------------------------------------------------
extern "C" void kernel_launch(void* const* d_in, const int* in_sizes, int n_in,
                              void* d_out, int out_size) {
    const float* x      = (const float*)d_in[0];
    const float* qkv_w  = (const float*)d_in[1];
    const float* qkv_b  = (const float*)d_in[2];
    const float* proj_w = (const float*)d_in[3];
    const float* proj_b = (const float*)d_in[4];
    const float* lscale = (const float*)d_in[5];
    const float* cpb_w1 = (const float*)d_in[6];
    const float* cpb_b1 = (const float*)d_in[7];
    const float* cpb_w2 = (const float*)d_in[8];
    const float* n1g    = (const float*)d_in[9];
    const float* n1b    = (const float*)d_in[10];
    const float* n2g    = (const float*)d_in[11];
    const float* n2b    = (const float*)d_in[12];
    const float* fc1_w  = (const float*)d_in[13];
    const float* fc1_b  = (const float*)d_in[14];
    const float* fc2_w  = (const float*)d_in[15];
    const float* fc2_b  = (const float*)d_in[16];
    float* out = (float*)d_out;

    cudaFuncSetAttribute(swin_kernel, cudaFuncAttributeMaxDynamicSharedMemorySize, SMEM_BYTES);

    bias_kernel<<<1, NTHREADS>>>(cpb_w1, cpb_b1, cpb_w2, lscale);
    swin_kernel<<<8192, NTHREADS, SMEM_BYTES>>>(x, qkv_w, qkv_b, proj_w, proj_b,
                                                n1g, n1b, n2g, n2b,
                                                fc1_w, fc1_b, fc2_w, fc2_b, out);
}

// round 5
// speedup vs baseline: 2.0402x; 1.5425x over previous
#include <cuda_runtime.h>
#include <cuda_bf16.h>
#include <cstdint>
#include <math.h>

// SwinTransformerBlockV2 fused kernel, v3b: channel GEMMs on tensor cores.
// Shift (8,8) is a multiple of window (4,4) => cyclic shift cancels and the
// attention mask is identically zero: plain aligned 4x4 window attention.
//
// GEMMs (qkv/proj/fc1/fc2) use mma.sync.m16n8k16 bf16 with a 2-term hi/lo
// split (3 MMAs per tile: Ah*Bh + Al*Bh + Ah*Bl) => ~fp32 accuracy.
// Weights pre-split into __device__ bf16 hi/lo arrays by a setup kernel.
// Activations split on the fly from f32 smem tiles.
// Attention / softmax / LN / GELU remain fp32 FFMA.

#define NTHREADS 256
#define LD   68
#define LDH2 132

#define OFF_X   0
#define OFF_Q   4352
#define OFF_K   8704
#define OFF_V   13056
#define OFF_W   17408
#define OFF_H   OFF_Q
#define OFF_WH  OFF_W
#define OFF_WL  (OFF_W + 4608)
#define OFF_ATT OFF_W
#define OFF_PH  (OFF_W + 4352)
#define OFF_PL  (OFF_W + 6656)
#define OFF_F2H OFF_W
#define OFF_F2L (OFF_W + 4352)
#define SMEM_FLOATS 26624
#define SMEM_BYTES  (SMEM_FLOATS * 4)

__device__ float g_bias[4 * 256];
__device__ float g_scale[4];

__device__ __nv_bfloat16 g_wqkv_h[192 * 64];
__device__ __nv_bfloat16 g_wqkv_l[192 * 64];
__device__ __nv_bfloat16 g_wproj_h[64 * 64];
__device__ __nv_bfloat16 g_wproj_l[64 * 64];
__device__ __nv_bfloat16 g_wfc1_h[256 * 64];
__device__ __nv_bfloat16 g_wfc1_l[256 * 64];
__device__ __nv_bfloat16 g_wfc2_h[64 * 256];
__device__ __nv_bfloat16 g_wfc2_l[64 * 256];

// ---------------------------------------------------------------------------
__device__ __forceinline__ float cpb_coord(int d) {
    float t = (8.0f / 3.0f) * (float)d;
    float v = log2f(fabsf(t) + 1.0f) / 3.0f;
    return (t < 0.0f) ? -v : v;
}

__global__ void bias_kernel(const float* __restrict__ w1, const float* __restrict__ b1,
                            const float* __restrict__ w2, const float* __restrict__ ls) {
    __shared__ float tab[49][4];
    int tid = threadIdx.x;
    for (int e = tid; e < 49 * 4; e += NTHREADS) {
        int q = e >> 2;
        int h = e & 3;
        int a = q / 7;
        int b = q % 7;
        float c0 = cpb_coord(a - 3);
        float c1 = cpb_coord(b - 3);
        float s = 0.0f;
        for (int j = 0; j < 512; j++) {
            float u = c0 * w1[2 * j] + c1 * w1[2 * j + 1] + b1[j];
            u = fmaxf(u, 0.0f);
            s += u * w2[h * 512 + j];
        }
        tab[q][h] = s;
    }
    __syncthreads();
    for (int e = tid; e < 4 * 256; e += NTHREADS) {
        int h = e >> 8;
        int n = (e >> 4) & 15;
        int m = e & 15;
        int idx = ((n >> 2) - (m >> 2) + 3) * 7 + ((n & 3) - (m & 3) + 3);
        float v = tab[idx][h];
        g_bias[h * 256 + n * 16 + m] = 16.0f / (1.0f + expf(-v));
    }
    if (tid < 4) g_scale[tid] = expf(fminf(ls[tid], logf(100.0f)));
}

__global__ void wsplit_kernel(const float* __restrict__ qkv_w, const float* __restrict__ proj_w,
                              const float* __restrict__ fc1_w, const float* __restrict__ fc2_w) {
    int i = blockIdx.x * NTHREADS + threadIdx.x;
    const float* src;
    __nv_bfloat16* dh;
    __nv_bfloat16* dl;
    int j = i;
    if (j < 12288) {
        src = qkv_w; dh = g_wqkv_h; dl = g_wqkv_l;
    } else if (j < 12288 + 4096) {
        j -= 12288; src = proj_w; dh = g_wproj_h; dl = g_wproj_l;
    } else if (j < 12288 + 4096 + 16384) {
        j -= 12288 + 4096; src = fc1_w; dh = g_wfc1_h; dl = g_wfc1_l;
    } else if (j < 12288 + 4096 + 16384 + 16384) {
        j -= 12288 + 4096 + 16384; src = fc2_w; dh = g_wfc2_h; dl = g_wfc2_l;
    } else {
        return;
    }
    float w = src[j];
    __nv_bfloat16 hi = __float2bfloat16_rn(w);
    dh[j] = hi;
    dl[j] = __float2bfloat16_rn(w - __bfloat162float(hi));
}

// ---------------------------------------------------------------------------
__device__ __forceinline__ void mma_bf16(float* dd,
        uint32_t a0, uint32_t a1, uint32_t a2, uint32_t a3,
        uint32_t b0, uint32_t b1) {
    asm volatile("mma.sync.aligned.m16n8k16.row.col.f32.bf16.bf16.f32 "
                 "{%0,%1,%2,%3}, {%4,%5,%6,%7}, {%8,%9}, {%0,%1,%2,%3};\n"
                 : "+f"(dd[0]), "+f"(dd[1]), "+f"(dd[2]), "+f"(dd[3])
                 : "r"(a0), "r"(a1), "r"(a2), "r"(a3), "r"(b0), "r"(b1));
}

__device__ __forceinline__ uint32_t split2(float x, float y, uint32_t& lo) {
    __nv_bfloat162 h2;
    h2.x = __float2bfloat16_rn(x);
    h2.y = __float2bfloat16_rn(y);
    __nv_bfloat162 l2;
    l2.x = __float2bfloat16_rn(x - __bfloat162float(h2.x));
    l2.y = __float2bfloat16_rn(y - __bfloat162float(h2.y));
    uint32_t hu, lu;
    memcpy(&hu, &h2, 4);
    memcpy(&lu, &l2, 4);
    lo = lu;
    return hu;
}

// C[16 x 8*NT] += A_f32[64][lda] x Wsplit^T  (3-term bf16 split)
template<int NT, int KSTEPS>
__device__ __forceinline__ void gemm_mma(const float* A, int lda, int mrow,
        const uint32_t* Bh, const uint32_t* Bl, int ldb, int nrow0,
        float (&d)[NT][4], int g, int t) {
#pragma unroll
    for (int ks = 0; ks < KSTEPS; ks++) {
        const float* ap = A + (mrow + g) * lda + ks * 16 + 2 * t;
        float2 p0 = *(const float2*)(ap);
        float2 p1 = *(const float2*)(ap + 8 * lda);
        float2 p2 = *(const float2*)(ap + 8);
        float2 p3 = *(const float2*)(ap + 8 * lda + 8);
        uint32_t al0, al1, al2, al3;
        uint32_t ah0 = split2(p0.x, p0.y, al0);
        uint32_t ah1 = split2(p1.x, p1.y, al1);
        uint32_t ah2 = split2(p2.x, p2.y, al2);
        uint32_t ah3 = split2(p3.x, p3.y, al3);
        int bk = ks * 8 + t;
#pragma unroll
        for (int j = 0; j < NT; j++) {
            int brow = (nrow0 + 8 * j + g) * ldb + bk;
            uint32_t bh0 = Bh[brow];
            uint32_t bh1 = Bh[brow + 4];
            uint32_t bl0 = Bl[brow];
            uint32_t bl1 = Bl[brow + 4];
            mma_bf16(d[j], ah0, ah1, ah2, ah3, bh0, bh1);
            mma_bf16(d[j], al0, al1, al2, al3, bh0, bh1);
            mma_bf16(d[j], ah0, ah1, ah2, ah3, bl0, bl1);
        }
    }
}

__device__ __forceinline__ void stage_w36(uint32_t* dh, uint32_t* dl,
        const __nv_bfloat16* gh, const __nv_bfloat16* gl, int rows, int tid) {
    const uint32_t* sh = (const uint32_t*)gh;
    const uint32_t* sl = (const uint32_t*)gl;
    for (int idx = tid; idx < rows * 32; idx += NTHREADS) {
        int r = idx >> 5;
        int c = idx & 31;
        dh[r * 36 + c] = sh[idx];
        dl[r * 36 + c] = sl[idx];
    }
}

__device__ __forceinline__ void stage_fc2(uint32_t* dh, uint32_t* dl, int kh, int tid) {
    const uint32_t* sh = (const uint32_t*)g_wfc2_h;
    const uint32_t* sl = (const uint32_t*)g_wfc2_l;
    for (int idx = tid; idx < 64 * 64; idx += NTHREADS) {
        int r = idx >> 6;
        int c = idx & 63;
        dh[r * 68 + c] = sh[r * 128 + kh * 64 + c];
        dl[r * 68 + c] = sl[r * 128 + kh * 64 + c];
    }
}

__device__ __forceinline__ int token_gaddr(int blk, int lt) {
    int wi = blk * 4 + (lt >> 4);
    int n  = lt & 15;
    int b  = wi >> 12;
    int r  = wi & 4095;
    int wh = r >> 6;
    int ww = r & 63;
    int row = wh * 4 + (n >> 2);
    int col = ww * 4 + (n & 3);
    return ((b * 256 + row) * 256 + col) * 64;
}

// ---------------------------------------------------------------------------
__global__ __launch_bounds__(NTHREADS, 2)
void swin_kernel(const float* __restrict__ x,
                 const float* __restrict__ qkv_b, const float* __restrict__ proj_b,
                 const float* __restrict__ n1g, const float* __restrict__ n1b,
                 const float* __restrict__ n2g, const float* __restrict__ n2b,
                 const float* __restrict__ fc1_b, const float* __restrict__ fc2_b,
                 float* __restrict__ out) {
    extern __shared__ float sm[];
    uint32_t* smu = (uint32_t*)sm;
    __shared__ float s_qkvb[192];
    __shared__ float s_projb[64];
    __shared__ float s_fc1b[256];
    __shared__ float s_fc2b[64];
    __shared__ float s_n1g[64];
    __shared__ float s_n1b[64];
    __shared__ float s_n2g[64];
    __shared__ float s_n2b[64];
    __shared__ float s_lnm[64];
    __shared__ float s_lnr[64];
    __shared__ float s_scale[4];

    const int tid  = threadIdx.x;
    const int warp = tid >> 5;
    const int lane = tid & 31;
    const int g = lane >> 2;
    const int t = lane & 3;
    const int mt = warp & 3;
    const int nh = warp >> 2;
    const int mrow = mt * 16;

    // ---- phase 0: params + x tile + qkv(QK) weight stage ----
    if (tid < 192) s_qkvb[tid] = (tid >= 64 && tid < 128) ? 0.0f : qkv_b[tid];
    if (tid < 64) {
        s_projb[tid] = proj_b[tid];
        s_fc2b[tid]  = fc2_b[tid];
        s_n1g[tid] = n1g[tid];
        s_n1b[tid] = n1b[tid];
        s_n2g[tid] = n2g[tid];
        s_n2b[tid] = n2b[tid];
    }
    s_fc1b[tid] = fc1_b[tid];
    if (tid >= 192 && tid < 196) s_scale[tid - 192] = g_scale[tid - 192];

    {
        int lt = tid >> 2;
        int pp = tid & 3;
        int gbase = token_gaddr(blockIdx.x, lt);
        const float4* xp = (const float4*)(x + gbase + pp * 16);
        float4* xd = (float4*)(sm + OFF_X + lt * LD + pp * 16);
#pragma unroll
        for (int i = 0; i < 4; i++) xd[i] = xp[i];
    }
    stage_w36(smu + OFF_WH, smu + OFF_WL, g_wqkv_h, g_wqkv_l, 128, tid);
    __syncthreads();

    // ---- phase 1: Q,K GEMM ----
    {
        float d[8][4];
#pragma unroll
        for (int j = 0; j < 8; j++) {
#pragma unroll
            for (int i = 0; i < 4; i++) d[j][i] = 0.0f;
        }
        gemm_mma<8, 4>(sm + OFF_X, LD, mrow, smu + OFF_WH, smu + OFF_WL, 36, nh * 64, d, g, t);
        float* dst = sm + (nh ? OFF_K : OFF_Q);
        const float* bias = s_qkvb + nh * 64;
#pragma unroll
        for (int j = 0; j < 8; j++) {
            int c = 8 * j + 2 * t;
            float b0 = bias[c];
            float b1 = bias[c + 1];
            *(float2*)(dst + (mrow + g) * LD + c)     = make_float2(d[j][0] + b0, d[j][1] + b1);
            *(float2*)(dst + (mrow + g + 8) * LD + c) = make_float2(d[j][2] + b0, d[j][3] + b1);
        }
    }
    __syncthreads();

    // ---- phase 2: V weight stage + V GEMM ----
    stage_w36(smu + OFF_WH, smu + OFF_WL, g_wqkv_h + 128 * 64, g_wqkv_l + 128 * 64, 64, tid);
    __syncthreads();
    {
        float d[4][4];
#pragma unroll
        for (int j = 0; j < 4; j++) {
#pragma unroll
            for (int i = 0; i < 4; i++) d[j][i] = 0.0f;
        }
        gemm_mma<4, 4>(sm + OFF_X, LD, mrow, smu + OFF_WH, smu + OFF_WL, 36, nh * 32, d, g, t);
#pragma unroll
        for (int j = 0; j < 4; j++) {
            int c = nh * 32 + 8 * j + 2 * t;
            float b0 = s_qkvb[128 + c];
            float b1 = s_qkvb[129 + c];
            *(float2*)(sm + OFF_V + (mrow + g) * LD + c)     = make_float2(d[j][0] + b0, d[j][1] + b1);
            *(float2*)(sm + OFF_V + (mrow + g + 8) * LD + c) = make_float2(d[j][2] + b0, d[j][3] + b1);
        }
    }
    __syncthreads();

    // ---- phase 3: cosine attention (half-warp per (window, head), fp32) ----
    {
        int hf = (tid >> 4) & 1;
        int task = warp * 2 + hf;
        int wl = task >> 2;
        int hh = task & 3;
        int sl = tid & 15;
        int trow = wl * 16 + sl;

        float qv[16];
        {
            const float4* qp = (const float4*)(sm + OFF_Q + trow * LD + hh * 16);
#pragma unroll
            for (int i = 0; i < 4; i++) {
                float4 v4 = qp[i];
                qv[4 * i] = v4.x; qv[4 * i + 1] = v4.y; qv[4 * i + 2] = v4.z; qv[4 * i + 3] = v4.w;
            }
            float ss = 0.0f;
#pragma unroll
            for (int d2 = 0; d2 < 16; d2++) ss += qv[d2] * qv[d2];
            float inv = s_scale[hh] * rsqrtf(fmaxf(ss, 1e-24f));
#pragma unroll
            for (int d2 = 0; d2 < 16; d2++) qv[d2] *= inv;
        }
        {
            float4* kp = (float4*)(sm + OFF_K + trow * LD + hh * 16);
            float kv[16];
#pragma unroll
            for (int i = 0; i < 4; i++) {
                float4 v4 = kp[i];
                kv[4 * i] = v4.x; kv[4 * i + 1] = v4.y; kv[4 * i + 2] = v4.z; kv[4 * i + 3] = v4.w;
            }
            float ss = 0.0f;
#pragma unroll
            for (int d2 = 0; d2 < 16; d2++) ss += kv[d2] * kv[d2];
            float inv = rsqrtf(fmaxf(ss, 1e-24f));
#pragma unroll
            for (int i = 0; i < 4; i++) {
                float4 v4;
                v4.x = kv[4 * i] * inv;
                v4.y = kv[4 * i + 1] * inv;
                v4.z = kv[4 * i + 2] * inv;
                v4.w = kv[4 * i + 3] * inv;
                kp[i] = v4;
            }
        }
        __syncwarp();

        float p[16];
        const float* bb = g_bias + hh * 256 + sl * 16;
#pragma unroll
        for (int c = 0; c < 16; c++) {
            const float4* kr = (const float4*)(sm + OFF_K + (wl * 16 + c) * LD + hh * 16);
            float s = bb[c];
#pragma unroll
            for (int i = 0; i < 4; i++) {
                float4 v4 = kr[i];
                s = fmaf(qv[4 * i], v4.x, fmaf(qv[4 * i + 1], v4.y,
                    fmaf(qv[4 * i + 2], v4.z, fmaf(qv[4 * i + 3], v4.w, s))));
            }
            p[c] = s;
        }
        float mx = p[0];
#pragma unroll
        for (int c = 1; c < 16; c++) mx = fmaxf(mx, p[c]);
        float sum = 0.0f;
#pragma unroll
        for (int c = 0; c < 16; c++) {
            p[c] = __expf(p[c] - mx);
            sum += p[c];
        }
        float invs = 1.0f / sum;

        float o[16];
#pragma unroll
        for (int d2 = 0; d2 < 16; d2++) o[d2] = 0.0f;
#pragma unroll
        for (int c = 0; c < 16; c++) {
            float pc = p[c] * invs;
            const float4* vp = (const float4*)(sm + OFF_V + (wl * 16 + c) * LD + hh * 16);
#pragma unroll
            for (int i = 0; i < 4; i++) {
                float4 v4 = vp[i];
                o[4 * i]     = fmaf(pc, v4.x, o[4 * i]);
                o[4 * i + 1] = fmaf(pc, v4.y, o[4 * i + 1]);
                o[4 * i + 2] = fmaf(pc, v4.z, o[4 * i + 2]);
                o[4 * i + 3] = fmaf(pc, v4.w, o[4 * i + 3]);
            }
        }
        float4* od = (float4*)(sm + OFF_ATT + trow * LD + hh * 16);
#pragma unroll
        for (int i = 0; i < 4; i++) {
            float4 v4;
            v4.x = o[4 * i];
            v4.y = o[4 * i + 1];
            v4.z = o[4 * i + 2];
            v4.w = o[4 * i + 3];
            od[i] = v4;
        }
    }
    stage_w36(smu + OFF_PH, smu + OFF_PL, g_wproj_h, g_wproj_l, 64, tid);
    __syncthreads();

    // ---- phase 4: proj GEMM -> 'a' into dead K buffer ----
    {
        float d[4][4];
#pragma unroll
        for (int j = 0; j < 4; j++) {
#pragma unroll
            for (int i = 0; i < 4; i++) d[j][i] = 0.0f;
        }
        gemm_mma<4, 4>(sm + OFF_ATT, LD, mrow, smu + OFF_PH, smu + OFF_PL, 36, nh * 32, d, g, t);
#pragma unroll
        for (int j = 0; j < 4; j++) {
            int c = nh * 32 + 8 * j + 2 * t;
            float b0 = s_projb[c];
            float b1 = s_projb[c + 1];
            *(float2*)(sm + OFF_K + (mrow + g) * LD + c)     = make_float2(d[j][0] + b0, d[j][1] + b1);
            *(float2*)(sm + OFF_K + (mrow + g + 8) * LD + c) = make_float2(d[j][2] + b0, d[j][3] + b1);
        }
    }
    __syncthreads();

    // ---- phase 5: LN1 + residual in place over x ----
    if (tid < 64) {
        const float* a = sm + OFF_K + tid * LD;
        float mean = 0.0f;
#pragma unroll
        for (int c = 0; c < 64; c++) mean += a[c];
        mean *= (1.0f / 64.0f);
        float var = 0.0f;
#pragma unroll
        for (int c = 0; c < 64; c++) {
            float d2 = a[c] - mean;
            var += d2 * d2;
        }
        var *= (1.0f / 64.0f);
        float rstd = rsqrtf(var + 1e-5f);
        float* xr = sm + OFF_X + tid * LD;
#pragma unroll
        for (int c = 0; c < 64; c++) {
            xr[c] = xr[c] + (a[c] - mean) * rstd * s_n1g[c] + s_n1b[c];
        }
    }
    __syncthreads();

    // ---- phase 6: MLP in two 128-wide halves, fc2 acc in fragments ----
    float d2acc[4][4];
#pragma unroll
    for (int j = 0; j < 4; j++) {
#pragma unroll
        for (int i = 0; i < 4; i++) d2acc[j][i] = 0.0f;
    }

#pragma unroll 1
    for (int kh = 0; kh < 2; kh++) {
        stage_w36(smu + OFF_WH, smu + OFF_WL, g_wfc1_h + kh * 128 * 64, g_wfc1_l + kh * 128 * 64, 128, tid);
        __syncthreads();
        {
            float d[8][4];
#pragma unroll
            for (int j = 0; j < 8; j++) {
#pragma unroll
                for (int i = 0; i < 4; i++) d[j][i] = 0.0f;
            }
            gemm_mma<8, 4>(sm + OFF_X, LD, mrow, smu + OFF_WH, smu + OFF_WL, 36, nh * 64, d, g, t);
#pragma unroll
            for (int j = 0; j < 8; j++) {
                int c = nh * 64 + 8 * j + 2 * t;
                float b0 = s_fc1b[kh * 128 + c];
                float b1 = s_fc1b[kh * 128 + c + 1];
#pragma unroll
                for (int i = 0; i < 4; i++) {
                    float v = d[j][i] + ((i & 1) ? b1 : b0);
                    d[j][i] = v * 0.5f * (1.0f + erff(v * 0.70710678118654752f));
                }
                *(float2*)(sm + OFF_H + (mrow + g) * LDH2 + c)     = make_float2(d[j][0], d[j][1]);
                *(float2*)(sm + OFF_H + (mrow + g + 8) * LDH2 + c) = make_float2(d[j][2], d[j][3]);
            }
        }
        __syncthreads();
        stage_fc2(smu + OFF_F2H, smu + OFF_F2L, kh, tid);
        __syncthreads();
        gemm_mma<4, 8>(sm + OFF_H, LDH2, mrow, smu + OFF_F2H, smu + OFF_F2L, 68, nh * 32, d2acc, g, t);
        __syncthreads();
    }

    // h2 -> dead V buffer
#pragma unroll
    for (int j = 0; j < 4; j++) {
        int c = nh * 32 + 8 * j + 2 * t;
        float b0 = s_fc2b[c];
        float b1 = s_fc2b[c + 1];
        *(float2*)(sm + OFF_V + (mrow + g) * LD + c)     = make_float2(d2acc[j][0] + b0, d2acc[j][1] + b1);
        *(float2*)(sm + OFF_V + (mrow + g + 8) * LD + c) = make_float2(d2acc[j][2] + b0, d2acc[j][3] + b1);
    }
    __syncthreads();

    // ---- phase 7: LN2 stats ----
    if (tid < 64) {
        const float* h2 = sm + OFF_V + tid * LD;
        float mean = 0.0f;
#pragma unroll
        for (int c = 0; c < 64; c++) mean += h2[c];
        mean *= (1.0f / 64.0f);
        float var = 0.0f;
#pragma unroll
        for (int c = 0; c < 64; c++) {
            float d2 = h2[c] - mean;
            var += d2 * d2;
        }
        var *= (1.0f / 64.0f);
        s_lnm[tid] = mean;
        s_lnr[tid] = rsqrtf(var + 1e-5f);
    }
    __syncthreads();

    // ---- phase 8: final residual + coalesced store ----
    {
        int lt = tid >> 2;
        int pp = tid & 3;
        int gbase = token_gaddr(blockIdx.x, lt);
        float m = s_lnm[lt];
        float r = s_lnr[lt];
#pragma unroll
        for (int q = 0; q < 4; q++) {
            int c = pp * 16 + q * 4;
            float4 xv = *(const float4*)(sm + OFF_X + lt * LD + c);
            float4 hv = *(const float4*)(sm + OFF_V + lt * LD + c);
            float4 ov;
            ov.x = xv.x + (hv.x - m) * r * s_n2g[c]     + s_n2b[c];
            ov.y = xv.y + (hv.y - m) * r * s_n2g[c + 1] + s_n2b[c + 1];
            ov.z = xv.z + (hv.z - m) * r * s_n2g[c + 2] + s_n2b[c + 2];
            ov.w = xv.w + (hv.w - m) * r * s_n2g[c + 3] + s_n2b[c + 3];
            *(float4*)(out + gbase + c) = ov;
        }
    }
}

// ---------------------------------------------------------------------------
extern "C" void kernel_launch(void* const* d_in, const int* in_sizes, int n_in,
                              void* d_out, int out_size) {
    const float* x      = (const float*)d_in[0];
    const float* qkv_w  = (const float*)d_in[1];
    const float* qkv_b  = (const float*)d_in[2];
    const float* proj_w = (const float*)d_in[3];
    const float* proj_b = (const float*)d_in[4];
    const float* lscale = (const float*)d_in[5];
    const float* cpb_w1 = (const float*)d_in[6];
    const float* cpb_b1 = (const float*)d_in[7];
    const float* cpb_w2 = (const float*)d_in[8];
    const float* n1g    = (const float*)d_in[9];
    const float* n1b    = (const float*)d_in[10];
    const float* n2g    = (const float*)d_in[11];
    const float* n2b    = (const float*)d_in[12];
    const float* fc1_w  = (const float*)d_in[13];
    const float* fc1_b  = (const float*)d_in[14];
    const float* fc2_w  = (const float*)d_in[15];
    const float* fc2_b  = (const float*)d_in[16];
    float* out = (float*)d_out;

    cudaFuncSetAttribute(swin_kernel, cudaFuncAttributeMaxDynamicSharedMemorySize, SMEM_BYTES);

    bias_kernel<<<1, NTHREADS>>>(cpb_w1, cpb_b1, cpb_w2, lscale);
    wsplit_kernel<<<192, NTHREADS>>>(qkv_w, proj_w, fc1_w, fc2_w);
    swin_kernel<<<8192, NTHREADS, SMEM_BYTES>>>(x, qkv_b, proj_b,
                                                n1g, n1b, n2g, n2b,
                                                fc1_b, fc2_b, out);
}

// round 6
// speedup vs baseline: 2.1024x; 1.0305x over previous
#include <cuda_runtime.h>
#include <cuda_bf16.h>
#include <cstdint>
#include <math.h>

// SwinTransformerBlockV2 fused kernel, v4.
// Shift (8,8) is a multiple of window (4,4) => cyclic shift cancels and the
// attention mask is identically zero: plain aligned 4x4 window attention.
//
// Channel GEMMs on mma.sync.m16n8k16 bf16 with 2-term hi/lo split (3 MMAs).
// v4: ATT and GELU outputs pre-split to bf16 in producer epilogues (proj/fc2
// A-operands become pure loads); parallel CPB setup; parallel LN phases;
// LN2 fused with final store.

#define NTHREADS 256
#define LD   68
#define LDH2 68   // u32 stride for H split (64 u32 data + 4 pad)

#define OFF_X   0
#define OFF_Q   4352
#define OFF_K   8704
#define OFF_V   13056
#define OFF_W   17408
// W-region sub-offsets
#define OFF_WH   OFF_W
#define OFF_WL   (OFF_W + 4608)
#define OFF_ATTH OFF_W
#define OFF_ATTL (OFF_W + 2304)
#define OFF_PH   (OFF_W + 4608)
#define OFF_PL   (OFF_W + 6912)
#define OFF_F2H  OFF_W
#define OFF_F2L  (OFF_W + 4352)
// H split overlays dead Q/K f32 regions
#define OFF_HH   OFF_Q
#define OFF_HL   OFF_K
#define SMEM_FLOATS 26624
#define SMEM_BYTES  (SMEM_FLOATS * 4)

__device__ float g_tab[49 * 4];
__device__ float g_bias[4 * 256];
__device__ float g_scale[4];

__device__ __nv_bfloat16 g_wqkv_h[192 * 64];
__device__ __nv_bfloat16 g_wqkv_l[192 * 64];
__device__ __nv_bfloat16 g_wproj_h[64 * 64];
__device__ __nv_bfloat16 g_wproj_l[64 * 64];
__device__ __nv_bfloat16 g_wfc1_h[256 * 64];
__device__ __nv_bfloat16 g_wfc1_l[256 * 64];
__device__ __nv_bfloat16 g_wfc2_h[64 * 256];
__device__ __nv_bfloat16 g_wfc2_l[64 * 256];

// ---------------------------------------------------------------------------
// Setup: CPB MLP (parallel), bias expand, weight split
// ---------------------------------------------------------------------------
__device__ __forceinline__ float cpb_coord(int d) {
    float t = (8.0f / 3.0f) * (float)d;
    float v = log2f(fabsf(t) + 1.0f) / 3.0f;
    return (t < 0.0f) ? -v : v;
}

__global__ void cpb_kernel(const float* __restrict__ w1, const float* __restrict__ b1,
                           const float* __restrict__ w2) {
    // one block per (q, h) table entry; 128 threads reduce the 512-dim dot
    int q = blockIdx.x >> 2;
    int h = blockIdx.x & 3;
    int a = q / 7;
    int b = q % 7;
    float c0 = cpb_coord(a - 3);
    float c1 = cpb_coord(b - 3);
    int tid = threadIdx.x;
    float s = 0.0f;
#pragma unroll
    for (int r = 0; r < 4; r++) {
        int j = tid + r * 128;
        float u = c0 * w1[2 * j] + c1 * w1[2 * j + 1] + b1[j];
        u = fmaxf(u, 0.0f);
        s += u * w2[h * 512 + j];
    }
    __shared__ float red[4];
#pragma unroll
    for (int o = 16; o > 0; o >>= 1) s += __shfl_xor_sync(0xffffffffu, s, o);
    if ((tid & 31) == 0) red[tid >> 5] = s;
    __syncthreads();
    if (tid == 0) g_tab[q * 4 + h] = red[0] + red[1] + red[2] + red[3];
}

__global__ void expand_kernel(const float* __restrict__ ls) {
    int e = blockIdx.x * 256 + threadIdx.x;
    int h = e >> 8;
    int n = (e >> 4) & 15;
    int m = e & 15;
    int idx = ((n >> 2) - (m >> 2) + 3) * 7 + ((n & 3) - (m & 3) + 3);
    float v = g_tab[idx * 4 + h];
    g_bias[h * 256 + n * 16 + m] = 16.0f / (1.0f + expf(-v));
    if (e < 4) g_scale[e] = expf(fminf(ls[e], logf(100.0f)));
}

__global__ void wsplit_kernel(const float* __restrict__ qkv_w, const float* __restrict__ proj_w,
                              const float* __restrict__ fc1_w, const float* __restrict__ fc2_w) {
    int i = blockIdx.x * NTHREADS + threadIdx.x;
    const float* src;
    __nv_bfloat16* dh;
    __nv_bfloat16* dl;
    int j = i;
    if (j < 12288) {
        src = qkv_w; dh = g_wqkv_h; dl = g_wqkv_l;
    } else if (j < 12288 + 4096) {
        j -= 12288; src = proj_w; dh = g_wproj_h; dl = g_wproj_l;
    } else if (j < 12288 + 4096 + 16384) {
        j -= 12288 + 4096; src = fc1_w; dh = g_wfc1_h; dl = g_wfc1_l;
    } else if (j < 12288 + 4096 + 16384 + 16384) {
        j -= 12288 + 4096 + 16384; src = fc2_w; dh = g_wfc2_h; dl = g_wfc2_l;
    } else {
        return;
    }
    float w = src[j];
    __nv_bfloat16 hi = __float2bfloat16_rn(w);
    dh[j] = hi;
    dl[j] = __float2bfloat16_rn(w - __bfloat162float(hi));
}

// ---------------------------------------------------------------------------
// mma helpers
// ---------------------------------------------------------------------------
__device__ __forceinline__ void mma_bf16(float* dd,
        uint32_t a0, uint32_t a1, uint32_t a2, uint32_t a3,
        uint32_t b0, uint32_t b1) {
    asm volatile("mma.sync.aligned.m16n8k16.row.col.f32.bf16.bf16.f32 "
                 "{%0,%1,%2,%3}, {%4,%5,%6,%7}, {%8,%9}, {%0,%1,%2,%3};\n"
                 : "+f"(dd[0]), "+f"(dd[1]), "+f"(dd[2]), "+f"(dd[3])
                 : "r"(a0), "r"(a1), "r"(a2), "r"(a3), "r"(b0), "r"(b1));
}

__device__ __forceinline__ uint32_t split2(float x, float y, uint32_t& lo) {
    __nv_bfloat162 h2;
    h2.x = __float2bfloat16_rn(x);
    h2.y = __float2bfloat16_rn(y);
    __nv_bfloat162 l2;
    l2.x = __float2bfloat16_rn(x - __bfloat162float(h2.x));
    l2.y = __float2bfloat16_rn(y - __bfloat162float(h2.y));
    uint32_t hu, lu;
    memcpy(&hu, &h2, 4);
    memcpy(&lu, &l2, 4);
    lo = lu;
    return hu;
}

// A = f32 smem tile, split on the fly
template<int NT, int KSTEPS>
__device__ __forceinline__ void gemm_mma_f32A(const float* A, int lda, int mrow,
        const uint32_t* Bh, const uint32_t* Bl, int ldb, int nrow0,
        float (&d)[NT][4], int g, int t) {
#pragma unroll
    for (int ks = 0; ks < KSTEPS; ks++) {
        const float* ap = A + (mrow + g) * lda + ks * 16 + 2 * t;
        float2 p0 = *(const float2*)(ap);
        float2 p1 = *(const float2*)(ap + 8 * lda);
        float2 p2 = *(const float2*)(ap + 8);
        float2 p3 = *(const float2*)(ap + 8 * lda + 8);
        uint32_t al0, al1, al2, al3;
        uint32_t ah0 = split2(p0.x, p0.y, al0);
        uint32_t ah1 = split2(p1.x, p1.y, al1);
        uint32_t ah2 = split2(p2.x, p2.y, al2);
        uint32_t ah3 = split2(p3.x, p3.y, al3);
        int bk = ks * 8 + t;
#pragma unroll
        for (int j = 0; j < NT; j++) {
            int brow = (nrow0 + 8 * j + g) * ldb + bk;
            uint32_t bh0 = Bh[brow];
            uint32_t bh1 = Bh[brow + 4];
            uint32_t bl0 = Bl[brow];
            uint32_t bl1 = Bl[brow + 4];
            mma_bf16(d[j], ah0, ah1, ah2, ah3, bh0, bh1);
            mma_bf16(d[j], al0, al1, al2, al3, bh0, bh1);
            mma_bf16(d[j], ah0, ah1, ah2, ah3, bl0, bl1);
        }
    }
}

// A = pre-split bf16 hi/lo u32 arrays
template<int NT, int KSTEPS>
__device__ __forceinline__ void gemm_mma_splitA(const uint32_t* Ah, const uint32_t* Al,
        int lda2, int mrow,
        const uint32_t* Bh, const uint32_t* Bl, int ldb, int nrow0,
        float (&d)[NT][4], int g, int t) {
#pragma unroll
    for (int ks = 0; ks < KSTEPS; ks++) {
        int ar = (mrow + g) * lda2 + ks * 8 + t;
        uint32_t ah0 = Ah[ar];
        uint32_t ah1 = Ah[ar + 8 * lda2];
        uint32_t ah2 = Ah[ar + 4];
        uint32_t ah3 = Ah[ar + 8 * lda2 + 4];
        uint32_t al0 = Al[ar];
        uint32_t al1 = Al[ar + 8 * lda2];
        uint32_t al2 = Al[ar + 4];
        uint32_t al3 = Al[ar + 8 * lda2 + 4];
        int bk = ks * 8 + t;
#pragma unroll
        for (int j = 0; j < NT; j++) {
            int brow = (nrow0 + 8 * j + g) * ldb + bk;
            uint32_t bh0 = Bh[brow];
            uint32_t bh1 = Bh[brow + 4];
            uint32_t bl0 = Bl[brow];
            uint32_t bl1 = Bl[brow + 4];
            mma_bf16(d[j], ah0, ah1, ah2, ah3, bh0, bh1);
            mma_bf16(d[j], al0, al1, al2, al3, bh0, bh1);
            mma_bf16(d[j], ah0, ah1, ah2, ah3, bl0, bl1);
        }
    }
}

__device__ __forceinline__ void stage_w36(uint32_t* dh, uint32_t* dl,
        const __nv_bfloat16* gh, const __nv_bfloat16* gl, int rows, int tid) {
    const uint32_t* sh = (const uint32_t*)gh;
    const uint32_t* sl = (const uint32_t*)gl;
    for (int idx = tid; idx < rows * 32; idx += NTHREADS) {
        int r = idx >> 5;
        int c = idx & 31;
        dh[r * 36 + c] = sh[idx];
        dl[r * 36 + c] = sl[idx];
    }
}

__device__ __forceinline__ void stage_fc2(uint32_t* dh, uint32_t* dl, int kh, int tid) {
    const uint32_t* sh = (const uint32_t*)g_wfc2_h;
    const uint32_t* sl = (const uint32_t*)g_wfc2_l;
    for (int idx = tid; idx < 64 * 64; idx += NTHREADS) {
        int r = idx >> 6;
        int c = idx & 63;
        dh[r * 68 + c] = sh[r * 128 + kh * 64 + c];
        dl[r * 68 + c] = sl[r * 128 + kh * 64 + c];
    }
}

__device__ __forceinline__ int token_gaddr(int blk, int lt) {
    int wi = blk * 4 + (lt >> 4);
    int n  = lt & 15;
    int b  = wi >> 12;
    int r  = wi & 4095;
    int wh = r >> 6;
    int ww = r & 63;
    int row = wh * 4 + (n >> 2);
    int col = ww * 4 + (n & 3);
    return ((b * 256 + row) * 256 + col) * 64;
}

// ---------------------------------------------------------------------------
__global__ __launch_bounds__(NTHREADS, 2)
void swin_kernel(const float* __restrict__ x,
                 const float* __restrict__ qkv_b, const float* __restrict__ proj_b,
                 const float* __restrict__ n1g, const float* __restrict__ n1b,
                 const float* __restrict__ n2g, const float* __restrict__ n2b,
                 const float* __restrict__ fc1_b, const float* __restrict__ fc2_b,
                 float* __restrict__ out) {
    extern __shared__ float sm[];
    uint32_t* smu = (uint32_t*)sm;
    __shared__ float s_qkvb[192];
    __shared__ float s_projb[64];
    __shared__ float s_fc1b[256];
    __shared__ float s_fc2b[64];
    __shared__ float s_n1g[64];
    __shared__ float s_n1b[64];
    __shared__ float s_n2g[64];
    __shared__ float s_n2b[64];
    __shared__ float s_scale[4];

    const int tid  = threadIdx.x;
    const int warp = tid >> 5;
    const int lane = tid & 31;
    const int g = lane >> 2;
    const int t = lane & 3;
    const int mt = warp & 3;
    const int nh = warp >> 2;
    const int mrow = mt * 16;

    // ---- phase 0: params + x tile + QK weight stage ----
    if (tid < 192) s_qkvb[tid] = (tid >= 64 && tid < 128) ? 0.0f : qkv_b[tid];
    if (tid < 64) {
        s_projb[tid] = proj_b[tid];
        s_fc2b[tid]  = fc2_b[tid];
        s_n1g[tid] = n1g[tid];
        s_n1b[tid] = n1b[tid];
        s_n2g[tid] = n2g[tid];
        s_n2b[tid] = n2b[tid];
    }
    s_fc1b[tid] = fc1_b[tid];
    if (tid >= 192 && tid < 196) s_scale[tid - 192] = g_scale[tid - 192];

    {
        int lt = tid >> 2;
        int pp = tid & 3;
        int gbase = token_gaddr(blockIdx.x, lt);
        const float4* xp = (const float4*)(x + gbase + pp * 16);
        float4* xd = (float4*)(sm + OFF_X + lt * LD + pp * 16);
#pragma unroll
        for (int i = 0; i < 4; i++) xd[i] = xp[i];
    }
    stage_w36(smu + OFF_WH, smu + OFF_WL, g_wqkv_h, g_wqkv_l, 128, tid);
    __syncthreads();

    // ---- phase 1: Q,K GEMM ----
    {
        float d[8][4];
#pragma unroll
        for (int j = 0; j < 8; j++) {
#pragma unroll
            for (int i = 0; i < 4; i++) d[j][i] = 0.0f;
        }
        gemm_mma_f32A<8, 4>(sm + OFF_X, LD, mrow, smu + OFF_WH, smu + OFF_WL, 36, nh * 64, d, g, t);
        float* dst = sm + (nh ? OFF_K : OFF_Q);
        const float* bias = s_qkvb + nh * 64;
#pragma unroll
        for (int j = 0; j < 8; j++) {
            int c = 8 * j + 2 * t;
            float b0 = bias[c];
            float b1 = bias[c + 1];
            *(float2*)(dst + (mrow + g) * LD + c)     = make_float2(d[j][0] + b0, d[j][1] + b1);
            *(float2*)(dst + (mrow + g + 8) * LD + c) = make_float2(d[j][2] + b0, d[j][3] + b1);
        }
    }
    __syncthreads();

    // ---- phase 2: V weight stage + V GEMM ----
    stage_w36(smu + OFF_WH, smu + OFF_WL, g_wqkv_h + 128 * 64, g_wqkv_l + 128 * 64, 64, tid);
    __syncthreads();
    {
        float d[4][4];
#pragma unroll
        for (int j = 0; j < 4; j++) {
#pragma unroll
            for (int i = 0; i < 4; i++) d[j][i] = 0.0f;
        }
        gemm_mma_f32A<4, 4>(sm + OFF_X, LD, mrow, smu + OFF_WH, smu + OFF_WL, 36, nh * 32, d, g, t);
#pragma unroll
        for (int j = 0; j < 4; j++) {
            int c = nh * 32 + 8 * j + 2 * t;
            float b0 = s_qkvb[128 + c];
            float b1 = s_qkvb[129 + c];
            *(float2*)(sm + OFF_V + (mrow + g) * LD + c)     = make_float2(d[j][0] + b0, d[j][1] + b1);
            *(float2*)(sm + OFF_V + (mrow + g + 8) * LD + c) = make_float2(d[j][2] + b0, d[j][3] + b1);
        }
    }
    __syncthreads();

    // ---- phase 3: cosine attention (half-warp per (window, head), fp32) ----
    {
        int hf = (tid >> 4) & 1;
        int task = warp * 2 + hf;
        int wl = task >> 2;
        int hh = task & 3;
        int sl = tid & 15;
        int trow = wl * 16 + sl;

        float qv[16];
        {
            const float4* qp = (const float4*)(sm + OFF_Q + trow * LD + hh * 16);
#pragma unroll
            for (int i = 0; i < 4; i++) {
                float4 v4 = qp[i];
                qv[4 * i] = v4.x; qv[4 * i + 1] = v4.y; qv[4 * i + 2] = v4.z; qv[4 * i + 3] = v4.w;
            }
            float ss = 0.0f;
#pragma unroll
            for (int d2 = 0; d2 < 16; d2++) ss += qv[d2] * qv[d2];
            float inv = s_scale[hh] * rsqrtf(fmaxf(ss, 1e-24f));
#pragma unroll
            for (int d2 = 0; d2 < 16; d2++) qv[d2] *= inv;
        }
        {
            float4* kp = (float4*)(sm + OFF_K + trow * LD + hh * 16);
            float kv[16];
#pragma unroll
            for (int i = 0; i < 4; i++) {
                float4 v4 = kp[i];
                kv[4 * i] = v4.x; kv[4 * i + 1] = v4.y; kv[4 * i + 2] = v4.z; kv[4 * i + 3] = v4.w;
            }
            float ss = 0.0f;
#pragma unroll
            for (int d2 = 0; d2 < 16; d2++) ss += kv[d2] * kv[d2];
            float inv = rsqrtf(fmaxf(ss, 1e-24f));
#pragma unroll
            for (int i = 0; i < 4; i++) {
                float4 v4;
                v4.x = kv[4 * i] * inv;
                v4.y = kv[4 * i + 1] * inv;
                v4.z = kv[4 * i + 2] * inv;
                v4.w = kv[4 * i + 3] * inv;
                kp[i] = v4;
            }
        }
        __syncwarp();

        float p[16];
        const float* bb = g_bias + hh * 256 + sl * 16;
#pragma unroll
        for (int c = 0; c < 16; c++) {
            const float4* kr = (const float4*)(sm + OFF_K + (wl * 16 + c) * LD + hh * 16);
            float s = bb[c];
#pragma unroll
            for (int i = 0; i < 4; i++) {
                float4 v4 = kr[i];
                s = fmaf(qv[4 * i], v4.x, fmaf(qv[4 * i + 1], v4.y,
                    fmaf(qv[4 * i + 2], v4.z, fmaf(qv[4 * i + 3], v4.w, s))));
            }
            p[c] = s;
        }
        float mx = p[0];
#pragma unroll
        for (int c = 1; c < 16; c++) mx = fmaxf(mx, p[c]);
        float sum = 0.0f;
#pragma unroll
        for (int c = 0; c < 16; c++) {
            p[c] = __expf(p[c] - mx);
            sum += p[c];
        }
        float invs = 1.0f / sum;

        float o[16];
#pragma unroll
        for (int d2 = 0; d2 < 16; d2++) o[d2] = 0.0f;
#pragma unroll
        for (int c = 0; c < 16; c++) {
            float pc = p[c] * invs;
            const float4* vp = (const float4*)(sm + OFF_V + (wl * 16 + c) * LD + hh * 16);
#pragma unroll
            for (int i = 0; i < 4; i++) {
                float4 v4 = vp[i];
                o[4 * i]     = fmaf(pc, v4.x, o[4 * i]);
                o[4 * i + 1] = fmaf(pc, v4.y, o[4 * i + 1]);
                o[4 * i + 2] = fmaf(pc, v4.z, o[4 * i + 2]);
                o[4 * i + 3] = fmaf(pc, v4.w, o[4 * i + 3]);
            }
        }
        // epilogue: split ATT row to bf16 hi/lo pairs ([64][36] u32 layout)
#pragma unroll
        for (int i = 0; i < 8; i++) {
            uint32_t lo;
            uint32_t hi = split2(o[2 * i], o[2 * i + 1], lo);
            smu[OFF_ATTH + trow * 36 + hh * 8 + i] = hi;
            smu[OFF_ATTL + trow * 36 + hh * 8 + i] = lo;
        }
    }
    // stage proj weights into upper W region (V weights dead; disjoint from ATT split)
    stage_w36(smu + OFF_PH, smu + OFF_PL, g_wproj_h, g_wproj_l, 64, tid);
    __syncthreads();

    // ---- phase 4: proj GEMM (A = pre-split ATT) -> 'a' into dead K buffer ----
    {
        float d[4][4];
#pragma unroll
        for (int j = 0; j < 4; j++) {
#pragma unroll
            for (int i = 0; i < 4; i++) d[j][i] = 0.0f;
        }
        gemm_mma_splitA<4, 4>(smu + OFF_ATTH, smu + OFF_ATTL, 36, mrow,
                              smu + OFF_PH, smu + OFF_PL, 36, nh * 32, d, g, t);
#pragma unroll
        for (int j = 0; j < 4; j++) {
            int c = nh * 32 + 8 * j + 2 * t;
            float b0 = s_projb[c];
            float b1 = s_projb[c + 1];
            *(float2*)(sm + OFF_K + (mrow + g) * LD + c)     = make_float2(d[j][0] + b0, d[j][1] + b1);
            *(float2*)(sm + OFF_K + (mrow + g + 8) * LD + c) = make_float2(d[j][2] + b0, d[j][3] + b1);
        }
    }
    __syncthreads();

    // ---- phase 5: LN1 + residual in place over x (4 threads per row) ----
    {
        int row = tid >> 2;
        int sub = tid & 3;
        const float* a = sm + OFF_K + row * LD + sub * 16;
        float s = 0.0f;
#pragma unroll
        for (int c = 0; c < 16; c++) s += a[c];
        s += __shfl_xor_sync(0xffffffffu, s, 1);
        s += __shfl_xor_sync(0xffffffffu, s, 2);
        float mean = s * (1.0f / 64.0f);
        float vv = 0.0f;
#pragma unroll
        for (int c = 0; c < 16; c++) {
            float d2 = a[c] - mean;
            vv += d2 * d2;
        }
        vv += __shfl_xor_sync(0xffffffffu, vv, 1);
        vv += __shfl_xor_sync(0xffffffffu, vv, 2);
        float rstd = rsqrtf(vv * (1.0f / 64.0f) + 1e-5f);
        float* xr = sm + OFF_X + row * LD + sub * 16;
        const float* gg = s_n1g + sub * 16;
        const float* bb = s_n1b + sub * 16;
#pragma unroll
        for (int c = 0; c < 16; c++) {
            xr[c] = xr[c] + (a[c] - mean) * rstd * gg[c] + bb[c];
        }
    }
    __syncthreads();

    // ---- phase 6: MLP in two 128-wide halves, fc2 acc in fragments ----
    float d2acc[4][4];
#pragma unroll
    for (int j = 0; j < 4; j++) {
#pragma unroll
        for (int i = 0; i < 4; i++) d2acc[j][i] = 0.0f;
    }

#pragma unroll 1
    for (int kh = 0; kh < 2; kh++) {
        stage_w36(smu + OFF_WH, smu + OFF_WL, g_wfc1_h + kh * 128 * 64, g_wfc1_l + kh * 128 * 64, 128, tid);
        __syncthreads();
        {
            float d[8][4];
#pragma unroll
            for (int j = 0; j < 8; j++) {
#pragma unroll
                for (int i = 0; i < 4; i++) d[j][i] = 0.0f;
            }
            gemm_mma_f32A<8, 4>(sm + OFF_X, LD, mrow, smu + OFF_WH, smu + OFF_WL, 36, nh * 64, d, g, t);
#pragma unroll
            for (int j = 0; j < 8; j++) {
                int c = nh * 64 + 8 * j + 2 * t;
                float b0 = s_fc1b[kh * 128 + c];
                float b1 = s_fc1b[kh * 128 + c + 1];
#pragma unroll
                for (int i = 0; i < 4; i++) {
                    float v = d[j][i] + ((i & 1) ? b1 : b0);
                    d[j][i] = v * 0.5f * (1.0f + erff(v * 0.70710678118654752f));
                }
                // gelu epilogue: split to bf16 hi/lo, store u32 pairs
                int col2 = nh * 32 + 4 * j + t;
                uint32_t lo0, lo1;
                uint32_t hi0 = split2(d[j][0], d[j][1], lo0);
                uint32_t hi1 = split2(d[j][2], d[j][3], lo1);
                smu[OFF_HH + (mrow + g) * LDH2 + col2]     = hi0;
                smu[OFF_HL + (mrow + g) * LDH2 + col2]     = lo0;
                smu[OFF_HH + (mrow + g + 8) * LDH2 + col2] = hi1;
                smu[OFF_HL + (mrow + g + 8) * LDH2 + col2] = lo1;
            }
        }
        __syncthreads();
        stage_fc2(smu + OFF_F2H, smu + OFF_F2L, kh, tid);
        __syncthreads();
        gemm_mma_splitA<4, 8>(smu + OFF_HH, smu + OFF_HL, LDH2, mrow,
                              smu + OFF_F2H, smu + OFF_F2L, 68, nh * 32, d2acc, g, t);
        __syncthreads();
    }

    // h2 -> dead V buffer
#pragma unroll
    for (int j = 0; j < 4; j++) {
        int c = nh * 32 + 8 * j + 2 * t;
        float b0 = s_fc2b[c];
        float b1 = s_fc2b[c + 1];
        *(float2*)(sm + OFF_V + (mrow + g) * LD + c)     = make_float2(d2acc[j][0] + b0, d2acc[j][1] + b1);
        *(float2*)(sm + OFF_V + (mrow + g + 8) * LD + c) = make_float2(d2acc[j][2] + b0, d2acc[j][3] + b1);
    }
    __syncthreads();

    // ---- phase 7: LN2 stats fused with final residual + store ----
    {
        int row = tid >> 2;
        int pp = tid & 3;
        const float* h2 = sm + OFF_V + row * LD + pp * 16;
        float s = 0.0f;
#pragma unroll
        for (int c = 0; c < 16; c++) s += h2[c];
        s += __shfl_xor_sync(0xffffffffu, s, 1);
        s += __shfl_xor_sync(0xffffffffu, s, 2);
        float mean = s * (1.0f / 64.0f);
        float vv = 0.0f;
#pragma unroll
        for (int c = 0; c < 16; c++) {
            float d2 = h2[c] - mean;
            vv += d2 * d2;
        }
        vv += __shfl_xor_sync(0xffffffffu, vv, 1);
        vv += __shfl_xor_sync(0xffffffffu, vv, 2);
        float rstd = rsqrtf(vv * (1.0f / 64.0f) + 1e-5f);

        int gbase = token_gaddr(blockIdx.x, row);
#pragma unroll
        for (int q = 0; q < 4; q++) {
            int c = pp * 16 + q * 4;
            float4 xv = *(const float4*)(sm + OFF_X + row * LD + c);
            float4 hv = *(const float4*)(sm + OFF_V + row * LD + c);
            float4 ov;
            ov.x = xv.x + (hv.x - mean) * rstd * s_n2g[c]     + s_n2b[c];
            ov.y = xv.y + (hv.y - mean) * rstd * s_n2g[c + 1] + s_n2b[c + 1];
            ov.z = xv.z + (hv.z - mean) * rstd * s_n2g[c + 2] + s_n2b[c + 2];
            ov.w = xv.w + (hv.w - mean) * rstd * s_n2g[c + 3] + s_n2b[c + 3];
            *(float4*)(out + gbase + c) = ov;
        }
    }
}

// ---------------------------------------------------------------------------
extern "C" void kernel_launch(void* const* d_in, const int* in_sizes, int n_in,
                              void* d_out, int out_size) {
    const float* x      = (const float*)d_in[0];
    const float* qkv_w  = (const float*)d_in[1];
    const float* qkv_b  = (const float*)d_in[2];
    const float* proj_w = (const float*)d_in[3];
    const float* proj_b = (const float*)d_in[4];
    const float* lscale = (const float*)d_in[5];
    const float* cpb_w1 = (const float*)d_in[6];
    const float* cpb_b1 = (const float*)d_in[7];
    const float* cpb_w2 = (const float*)d_in[8];
    const float* n1g    = (const float*)d_in[9];
    const float* n1b    = (const float*)d_in[10];
    const float* n2g    = (const float*)d_in[11];
    const float* n2b    = (const float*)d_in[12];
    const float* fc1_w  = (const float*)d_in[13];
    const float* fc1_b  = (const float*)d_in[14];
    const float* fc2_w  = (const float*)d_in[15];
    const float* fc2_b  = (const float*)d_in[16];
    float* out = (float*)d_out;

    cudaFuncSetAttribute(swin_kernel, cudaFuncAttributeMaxDynamicSharedMemorySize, SMEM_BYTES);

    cpb_kernel<<<196, 128>>>(cpb_w1, cpb_b1, cpb_w2);
    expand_kernel<<<4, 256>>>(lscale);
    wsplit_kernel<<<192, NTHREADS>>>(qkv_w, proj_w, fc1_w, fc2_w);
    swin_kernel<<<8192, NTHREADS, SMEM_BYTES>>>(x, qkv_b, proj_b,
                                                n1g, n1b, n2g, n2b,
                                                fc1_b, fc2_b, out);
}

// round 7
// speedup vs baseline: 2.7110x; 1.2895x over previous
#include <cuda_runtime.h>
#include <cuda_bf16.h>
#include <cstdint>
#include <math.h>

// SwinTransformerBlockV2 fused kernel, v5.
// Shift (8,8) multiple of window (4,4) => shift cancels, mask == 0.
// Channel GEMMs: mma.sync.m16n8k16 bf16, 2-term hi/lo split (3 MMAs/tile).
// v5: B-fragments loaded directly from a fragment-ready global layout
// (no smem weight staging); per-phase warp decomposition tuned to minimize
// redundant operand traffic; fast bf16x2 split.

#define NTHREADS 256
#define LD   68
#define LDH2 68

#define OFF_X    0
#define OFF_Q    4352
#define OFF_K    8704
#define OFF_V    13056
#define OFF_ATTH 17408
#define OFF_ATTL 19712
#define OFF_HH   OFF_Q
#define OFF_HL   OFF_K
#define SMEM_FLOATS 22016
#define SMEM_BYTES  (SMEM_FLOATS * 4)

__device__ float g_tab[49 * 4];
__device__ float g_bias[4 * 256];
__device__ float g_scale[4];

// fragment-ready weights: per (octet o, kstep ks, g, t) a uint4
// { hi(k-pair ks*8+t), hi(ks*8+t+4), lo(ks*8+t), lo(ks*8+t+4) } for n = o*8+g
__device__ uint4 g_fqkv[3072];   // 192x64,  KS=4,  O=24
__device__ uint4 g_fproj[1024];  // 64x64,   KS=4,  O=8
__device__ uint4 g_ffc1[4096];   // 256x64,  KS=4,  O=32
__device__ uint4 g_ffc2[4096];   // 64x256,  KS=16, O=8

// ---------------------------------------------------------------------------
// Setup kernels
// ---------------------------------------------------------------------------
__device__ __forceinline__ float cpb_coord(int d) {
    float t = (8.0f / 3.0f) * (float)d;
    float v = log2f(fabsf(t) + 1.0f) / 3.0f;
    return (t < 0.0f) ? -v : v;
}

__global__ void cpb_kernel(const float* __restrict__ w1, const float* __restrict__ b1,
                           const float* __restrict__ w2) {
    int q = blockIdx.x >> 2;
    int h = blockIdx.x & 3;
    int a = q / 7;
    int b = q % 7;
    float c0 = cpb_coord(a - 3);
    float c1 = cpb_coord(b - 3);
    int tid = threadIdx.x;
    float s = 0.0f;
#pragma unroll
    for (int r = 0; r < 4; r++) {
        int j = tid + r * 128;
        float u = c0 * w1[2 * j] + c1 * w1[2 * j + 1] + b1[j];
        u = fmaxf(u, 0.0f);
        s += u * w2[h * 512 + j];
    }
    __shared__ float red[4];
#pragma unroll
    for (int o = 16; o > 0; o >>= 1) s += __shfl_xor_sync(0xffffffffu, s, o);
    if ((tid & 31) == 0) red[tid >> 5] = s;
    __syncthreads();
    if (tid == 0) g_tab[q * 4 + h] = red[0] + red[1] + red[2] + red[3];
}

__global__ void expand_kernel(const float* __restrict__ ls) {
    int e = blockIdx.x * 256 + threadIdx.x;
    int h = e >> 8;
    int n = (e >> 4) & 15;
    int m = e & 15;
    int idx = ((n >> 2) - (m >> 2) + 3) * 7 + ((n & 3) - (m & 3) + 3);
    float v = g_tab[idx * 4 + h];
    g_bias[h * 256 + n * 16 + m] = 16.0f / (1.0f + expf(-v));
    if (e < 4) g_scale[e] = expf(fminf(ls[e], logf(100.0f)));
}

__device__ __forceinline__ uint32_t pack_split(float x, float y, uint32_t& lo) {
    uint32_t hi;
    asm("cvt.rn.bf16x2.f32 %0, %1, %2;" : "=r"(hi) : "f"(y), "f"(x));
    float hx = __uint_as_float(hi << 16);
    float hy = __uint_as_float(hi & 0xffff0000u);
    asm("cvt.rn.bf16x2.f32 %0, %1, %2;" : "=r"(lo) : "f"(y - hy), "f"(x - hx));
    return hi;
}

__global__ void wsplit_kernel(const float* __restrict__ qkv_w, const float* __restrict__ proj_w,
                              const float* __restrict__ fc1_w, const float* __restrict__ fc2_w) {
    int i = blockIdx.x * 256 + threadIdx.x;
    const float* src;
    uint4* dst;
    int q, K, lgKS;
    if (i < 3072) {
        q = i; src = qkv_w; dst = g_fqkv; K = 64; lgKS = 2;
    } else if (i < 4096) {
        q = i - 3072; src = proj_w; dst = g_fproj; K = 64; lgKS = 2;
    } else if (i < 8192) {
        q = i - 4096; src = fc1_w; dst = g_ffc1; K = 64; lgKS = 2;
    } else if (i < 12288) {
        q = i - 8192; src = fc2_w; dst = g_ffc2; K = 256; lgKS = 4;
    } else {
        return;
    }
    int t  = q & 3;
    int g  = (q >> 2) & 7;
    int ks = (q >> 5) & ((1 << lgKS) - 1);
    int o  = q >> (5 + lgKS);
    int n  = o * 8 + g;
    int p0 = ks * 8 + t;        // u32-pair index (2 bf16 = 2 floats)
    int p1 = p0 + 4;
    const float* row = src + n * K;
    uint32_t lo0, lo1;
    uint32_t hi0 = pack_split(row[2 * p0], row[2 * p0 + 1], lo0);
    uint32_t hi1 = pack_split(row[2 * p1], row[2 * p1 + 1], lo1);
    dst[q] = make_uint4(hi0, hi1, lo0, lo1);
}

// ---------------------------------------------------------------------------
// mma helpers
// ---------------------------------------------------------------------------
__device__ __forceinline__ void mma_bf16(float* dd,
        uint32_t a0, uint32_t a1, uint32_t a2, uint32_t a3,
        uint32_t b0, uint32_t b1) {
    asm volatile("mma.sync.aligned.m16n8k16.row.col.f32.bf16.bf16.f32 "
                 "{%0,%1,%2,%3}, {%4,%5,%6,%7}, {%8,%9}, {%0,%1,%2,%3};\n"
                 : "+f"(dd[0]), "+f"(dd[1]), "+f"(dd[2]), "+f"(dd[3])
                 : "r"(a0), "r"(a1), "r"(a2), "r"(a3), "r"(b0), "r"(b1));
}

__device__ __forceinline__ uint32_t split2(float x, float y, uint32_t& lo) {
    return pack_split(x, y, lo);
}

// M2 (two m16 tiles per warp), A = f32 smem tile (stride LD), B direct global frags
template<int NT, int KSTEPS>
__device__ __forceinline__ void gemm2_f32A(const float* A, int mrow,
        const uint4* __restrict__ Bf, int KS_total, int ks0, int o0,
        float (&d)[2][NT][4], int g, int t) {
#pragma unroll
    for (int ks = 0; ks < KSTEPS; ks++) {
        uint32_t ah[2][4], al[2][4];
#pragma unroll
        for (int i2 = 0; i2 < 2; i2++) {
            const float* ap = A + (mrow + i2 * 16 + g) * LD + ks * 16 + 2 * t;
            float2 p0 = *(const float2*)(ap);
            float2 p1 = *(const float2*)(ap + 8 * LD);
            float2 p2 = *(const float2*)(ap + 8);
            float2 p3 = *(const float2*)(ap + 8 * LD + 8);
            ah[i2][0] = split2(p0.x, p0.y, al[i2][0]);
            ah[i2][1] = split2(p1.x, p1.y, al[i2][1]);
            ah[i2][2] = split2(p2.x, p2.y, al[i2][2]);
            ah[i2][3] = split2(p3.x, p3.y, al[i2][3]);
        }
        int base = (ks0 + ks) * 32 + g * 4 + t;
#pragma unroll
        for (int j = 0; j < NT; j++) {
            uint4 b = Bf[(o0 + j) * (KS_total * 32) + base];
#pragma unroll
            for (int i2 = 0; i2 < 2; i2++) {
                mma_bf16(d[i2][j], ah[i2][0], ah[i2][1], ah[i2][2], ah[i2][3], b.x, b.y);
                mma_bf16(d[i2][j], al[i2][0], al[i2][1], al[i2][2], al[i2][3], b.x, b.y);
                mma_bf16(d[i2][j], ah[i2][0], ah[i2][1], ah[i2][2], ah[i2][3], b.z, b.w);
            }
        }
    }
}

// M1 (one m16 tile), A = pre-split bf16 hi/lo u32 smem arrays, B direct global frags
template<int NT, int KSTEPS>
__device__ __forceinline__ void gemm1_splitA(const uint32_t* Ah, const uint32_t* Al,
        int lda2, int mrow,
        const uint4* __restrict__ Bf, int KS_total, int ks0, int o0,
        float (&d)[NT][4], int g, int t) {
#pragma unroll
    for (int ks = 0; ks < KSTEPS; ks++) {
        int ar = (mrow + g) * lda2 + ks * 8 + t;
        uint32_t ah0 = Ah[ar];
        uint32_t ah1 = Ah[ar + 8 * lda2];
        uint32_t ah2 = Ah[ar + 4];
        uint32_t ah3 = Ah[ar + 8 * lda2 + 4];
        uint32_t al0 = Al[ar];
        uint32_t al1 = Al[ar + 8 * lda2];
        uint32_t al2 = Al[ar + 4];
        uint32_t al3 = Al[ar + 8 * lda2 + 4];
        int base = (ks0 + ks) * 32 + g * 4 + t;
#pragma unroll
        for (int j = 0; j < NT; j++) {
            uint4 b = Bf[(o0 + j) * (KS_total * 32) + base];
            mma_bf16(d[j], ah0, ah1, ah2, ah3, b.x, b.y);
            mma_bf16(d[j], al0, al1, al2, al3, b.x, b.y);
            mma_bf16(d[j], ah0, ah1, ah2, ah3, b.z, b.w);
        }
    }
}

__device__ __forceinline__ int token_gaddr(int blk, int lt) {
    int wi = blk * 4 + (lt >> 4);
    int n  = lt & 15;
    int b  = wi >> 12;
    int r  = wi & 4095;
    int wh = r >> 6;
    int ww = r & 63;
    int row = wh * 4 + (n >> 2);
    int col = ww * 4 + (n & 3);
    return ((b * 256 + row) * 256 + col) * 64;
}

// ---------------------------------------------------------------------------
__global__ __launch_bounds__(NTHREADS, 2)
void swin_kernel(const float* __restrict__ x,
                 const float* __restrict__ qkv_b, const float* __restrict__ proj_b,
                 const float* __restrict__ n1g, const float* __restrict__ n1b,
                 const float* __restrict__ n2g, const float* __restrict__ n2b,
                 const float* __restrict__ fc1_b, const float* __restrict__ fc2_b,
                 float* __restrict__ out) {
    extern __shared__ float sm[];
    uint32_t* smu = (uint32_t*)sm;
    __shared__ float s_qkvb[192];
    __shared__ float s_projb[64];
    __shared__ float s_fc1b[256];
    __shared__ float s_fc2b[64];
    __shared__ float s_n1g[64];
    __shared__ float s_n1b[64];
    __shared__ float s_n2g[64];
    __shared__ float s_n2b[64];
    __shared__ float s_scale[4];

    const int tid  = threadIdx.x;
    const int warp = tid >> 5;
    const int lane = tid & 31;
    const int g = lane >> 2;
    const int t = lane & 3;
    // M2 decomposition (QKV, fc1): 2 m-warps x 4 n-warps
    const int mt2 = warp >> 2;
    const int nh4 = warp & 3;
    const int mrow2 = mt2 * 32;
    // M1 decomposition (proj, fc2): 4 m-warps x 2 n-warps
    const int mt1 = warp & 3;
    const int nh1 = warp >> 2;
    const int mrow1 = mt1 * 16;

    // ---- phase 0: params + x tile ----
    if (tid < 192) s_qkvb[tid] = (tid >= 64 && tid < 128) ? 0.0f : qkv_b[tid];
    if (tid < 64) {
        s_projb[tid] = proj_b[tid];
        s_fc2b[tid]  = fc2_b[tid];
        s_n1g[tid] = n1g[tid];
        s_n1b[tid] = n1b[tid];
        s_n2g[tid] = n2g[tid];
        s_n2b[tid] = n2b[tid];
    }
    s_fc1b[tid] = fc1_b[tid];
    if (tid >= 192 && tid < 196) s_scale[tid - 192] = g_scale[tid - 192];

    {
        int lt = tid >> 2;
        int pp = tid & 3;
        int gbase = token_gaddr(blockIdx.x, lt);
        const float4* xp = (const float4*)(x + gbase + pp * 16);
        float4* xd = (float4*)(sm + OFF_X + lt * LD + pp * 16);
#pragma unroll
        for (int i = 0; i < 4; i++) xd[i] = xp[i];
    }
    __syncthreads();

    // ---- phase 1: QKV GEMM (M2, n-quarter = 48 cols = 6 octets) ----
    {
        float d[2][6][4];
#pragma unroll
        for (int i2 = 0; i2 < 2; i2++)
#pragma unroll
            for (int j = 0; j < 6; j++)
#pragma unroll
                for (int i = 0; i < 4; i++) d[i2][j][i] = 0.0f;
        gemm2_f32A<6, 4>(sm + OFF_X, mrow2, g_fqkv, 4, 0, nh4 * 6, d, g, t);
#pragma unroll
        for (int j = 0; j < 6; j++) {
            int c = nh4 * 48 + 8 * j + 2 * t;
            int blk = c >> 6;
            int col = c & 63;
            float* dst = sm + (blk == 0 ? OFF_Q : (blk == 1 ? OFF_K : OFF_V));
            float b0 = s_qkvb[c];
            float b1 = s_qkvb[c + 1];
#pragma unroll
            for (int i2 = 0; i2 < 2; i2++) {
                int r = mrow2 + i2 * 16 + g;
                *(float2*)(dst + r * LD + col)       = make_float2(d[i2][j][0] + b0, d[i2][j][1] + b1);
                *(float2*)(dst + (r + 8) * LD + col) = make_float2(d[i2][j][2] + b0, d[i2][j][3] + b1);
            }
        }
    }
    __syncthreads();

    // ---- phase 2: cosine attention (half-warp per (window, head), fp32) ----
    {
        int hf = (tid >> 4) & 1;
        int task = warp * 2 + hf;
        int wl = task >> 2;
        int hh = task & 3;
        int sl = tid & 15;
        int trow = wl * 16 + sl;

        float qv[16];
        {
            const float4* qp = (const float4*)(sm + OFF_Q + trow * LD + hh * 16);
#pragma unroll
            for (int i = 0; i < 4; i++) {
                float4 v4 = qp[i];
                qv[4 * i] = v4.x; qv[4 * i + 1] = v4.y; qv[4 * i + 2] = v4.z; qv[4 * i + 3] = v4.w;
            }
            float ss = 0.0f;
#pragma unroll
            for (int d2 = 0; d2 < 16; d2++) ss += qv[d2] * qv[d2];
            float inv = s_scale[hh] * rsqrtf(fmaxf(ss, 1e-24f));
#pragma unroll
            for (int d2 = 0; d2 < 16; d2++) qv[d2] *= inv;
        }
        {
            float4* kp = (float4*)(sm + OFF_K + trow * LD + hh * 16);
            float kv[16];
#pragma unroll
            for (int i = 0; i < 4; i++) {
                float4 v4 = kp[i];
                kv[4 * i] = v4.x; kv[4 * i + 1] = v4.y; kv[4 * i + 2] = v4.z; kv[4 * i + 3] = v4.w;
            }
            float ss = 0.0f;
#pragma unroll
            for (int d2 = 0; d2 < 16; d2++) ss += kv[d2] * kv[d2];
            float inv = rsqrtf(fmaxf(ss, 1e-24f));
#pragma unroll
            for (int i = 0; i < 4; i++) {
                float4 v4;
                v4.x = kv[4 * i] * inv;
                v4.y = kv[4 * i + 1] * inv;
                v4.z = kv[4 * i + 2] * inv;
                v4.w = kv[4 * i + 3] * inv;
                kp[i] = v4;
            }
        }
        __syncwarp();

        float p[16];
        const float* bb = g_bias + hh * 256 + sl * 16;
#pragma unroll
        for (int c = 0; c < 16; c++) {
            const float4* kr = (const float4*)(sm + OFF_K + (wl * 16 + c) * LD + hh * 16);
            float s = bb[c];
#pragma unroll
            for (int i = 0; i < 4; i++) {
                float4 v4 = kr[i];
                s = fmaf(qv[4 * i], v4.x, fmaf(qv[4 * i + 1], v4.y,
                    fmaf(qv[4 * i + 2], v4.z, fmaf(qv[4 * i + 3], v4.w, s))));
            }
            p[c] = s;
        }
        float mx = p[0];
#pragma unroll
        for (int c = 1; c < 16; c++) mx = fmaxf(mx, p[c]);
        float sum = 0.0f;
#pragma unroll
        for (int c = 0; c < 16; c++) {
            p[c] = __expf(p[c] - mx);
            sum += p[c];
        }
        float invs = 1.0f / sum;

        float o[16];
#pragma unroll
        for (int d2 = 0; d2 < 16; d2++) o[d2] = 0.0f;
#pragma unroll
        for (int c = 0; c < 16; c++) {
            float pc = p[c] * invs;
            const float4* vp = (const float4*)(sm + OFF_V + (wl * 16 + c) * LD + hh * 16);
#pragma unroll
            for (int i = 0; i < 4; i++) {
                float4 v4 = vp[i];
                o[4 * i]     = fmaf(pc, v4.x, o[4 * i]);
                o[4 * i + 1] = fmaf(pc, v4.y, o[4 * i + 1]);
                o[4 * i + 2] = fmaf(pc, v4.z, o[4 * i + 2]);
                o[4 * i + 3] = fmaf(pc, v4.w, o[4 * i + 3]);
            }
        }
        // epilogue: split ATT row to bf16 hi/lo ([64][36] u32 layout)
#pragma unroll
        for (int i = 0; i < 8; i++) {
            uint32_t lo;
            uint32_t hi = split2(o[2 * i], o[2 * i + 1], lo);
            smu[OFF_ATTH + trow * 36 + hh * 8 + i] = hi;
            smu[OFF_ATTL + trow * 36 + hh * 8 + i] = lo;
        }
    }
    __syncthreads();

    // ---- phase 3: proj GEMM (M1, A = pre-split ATT) -> 'a' into K buffer ----
    {
        float d[4][4];
#pragma unroll
        for (int j = 0; j < 4; j++)
#pragma unroll
            for (int i = 0; i < 4; i++) d[j][i] = 0.0f;
        gemm1_splitA<4, 4>(smu + OFF_ATTH, smu + OFF_ATTL, 36, mrow1,
                           g_fproj, 4, 0, nh1 * 4, d, g, t);
#pragma unroll
        for (int j = 0; j < 4; j++) {
            int c = nh1 * 32 + 8 * j + 2 * t;
            float b0 = s_projb[c];
            float b1 = s_projb[c + 1];
            *(float2*)(sm + OFF_K + (mrow1 + g) * LD + c)     = make_float2(d[j][0] + b0, d[j][1] + b1);
            *(float2*)(sm + OFF_K + (mrow1 + g + 8) * LD + c) = make_float2(d[j][2] + b0, d[j][3] + b1);
        }
    }
    __syncthreads();

    // ---- phase 4: LN1 + residual in place over x (4 threads per row) ----
    {
        int row = tid >> 2;
        int sub = tid & 3;
        const float* a = sm + OFF_K + row * LD + sub * 16;
        float s = 0.0f;
#pragma unroll
        for (int c = 0; c < 16; c++) s += a[c];
        s += __shfl_xor_sync(0xffffffffu, s, 1);
        s += __shfl_xor_sync(0xffffffffu, s, 2);
        float mean = s * (1.0f / 64.0f);
        float vv = 0.0f;
#pragma unroll
        for (int c = 0; c < 16; c++) {
            float d2 = a[c] - mean;
            vv += d2 * d2;
        }
        vv += __shfl_xor_sync(0xffffffffu, vv, 1);
        vv += __shfl_xor_sync(0xffffffffu, vv, 2);
        float rstd = rsqrtf(vv * (1.0f / 64.0f) + 1e-5f);
        float* xr = sm + OFF_X + row * LD + sub * 16;
        const float* gg = s_n1g + sub * 16;
        const float* bbv = s_n1b + sub * 16;
#pragma unroll
        for (int c = 0; c < 16; c++) {
            xr[c] = xr[c] + (a[c] - mean) * rstd * gg[c] + bbv[c];
        }
    }
    __syncthreads();

    // ---- phase 5: MLP in two 128-wide halves ----
    float dacc[4][4];
#pragma unroll
    for (int j = 0; j < 4; j++)
#pragma unroll
        for (int i = 0; i < 4; i++) dacc[j][i] = 0.0f;

#pragma unroll 1
    for (int kh = 0; kh < 2; kh++) {
        // fc1 half GEMM (M2) + gelu + split store -> H region
        {
            float d[2][4][4];
#pragma unroll
            for (int i2 = 0; i2 < 2; i2++)
#pragma unroll
                for (int j = 0; j < 4; j++)
#pragma unroll
                    for (int i = 0; i < 4; i++) d[i2][j][i] = 0.0f;
            gemm2_f32A<4, 4>(sm + OFF_X, mrow2, g_ffc1, 4, 0, kh * 16 + nh4 * 4, d, g, t);
#pragma unroll
            for (int j = 0; j < 4; j++) {
                int c = nh4 * 32 + 8 * j + 2 * t;
                float b0 = s_fc1b[kh * 128 + c];
                float b1 = s_fc1b[kh * 128 + c + 1];
                int col2 = nh4 * 16 + 4 * j + t;
#pragma unroll
                for (int i2 = 0; i2 < 2; i2++) {
                    float v0 = d[i2][j][0] + b0;
                    float v1 = d[i2][j][1] + b1;
                    float v2 = d[i2][j][2] + b0;
                    float v3 = d[i2][j][3] + b1;
                    v0 = v0 * 0.5f * (1.0f + erff(v0 * 0.70710678118654752f));
                    v1 = v1 * 0.5f * (1.0f + erff(v1 * 0.70710678118654752f));
                    v2 = v2 * 0.5f * (1.0f + erff(v2 * 0.70710678118654752f));
                    v3 = v3 * 0.5f * (1.0f + erff(v3 * 0.70710678118654752f));
                    int r = mrow2 + i2 * 16 + g;
                    uint32_t lo0, lo1;
                    uint32_t hi0 = split2(v0, v1, lo0);
                    uint32_t hi1 = split2(v2, v3, lo1);
                    smu[OFF_HH + r * LDH2 + col2]       = hi0;
                    smu[OFF_HL + r * LDH2 + col2]       = lo0;
                    smu[OFF_HH + (r + 8) * LDH2 + col2] = hi1;
                    smu[OFF_HL + (r + 8) * LDH2 + col2] = lo1;
                }
            }
        }
        __syncthreads();
        // fc2 partial GEMM (M1, A = split H), persistent fragments
        gemm1_splitA<4, 8>(smu + OFF_HH, smu + OFF_HL, LDH2, mrow1,
                           g_ffc2, 16, kh * 8, nh1 * 4, dacc, g, t);
        __syncthreads();
    }

    // h2 -> dead V buffer
#pragma unroll
    for (int j = 0; j < 4; j++) {
        int c = nh1 * 32 + 8 * j + 2 * t;
        float b0 = s_fc2b[c];
        float b1 = s_fc2b[c + 1];
        *(float2*)(sm + OFF_V + (mrow1 + g) * LD + c)     = make_float2(dacc[j][0] + b0, dacc[j][1] + b1);
        *(float2*)(sm + OFF_V + (mrow1 + g + 8) * LD + c) = make_float2(dacc[j][2] + b0, dacc[j][3] + b1);
    }
    __syncthreads();

    // ---- phase 6: LN2 fused with final residual + store ----
    {
        int row = tid >> 2;
        int pp = tid & 3;
        const float* h2 = sm + OFF_V + row * LD + pp * 16;
        float s = 0.0f;
#pragma unroll
        for (int c = 0; c < 16; c++) s += h2[c];
        s += __shfl_xor_sync(0xffffffffu, s, 1);
        s += __shfl_xor_sync(0xffffffffu, s, 2);
        float mean = s * (1.0f / 64.0f);
        float vv = 0.0f;
#pragma unroll
        for (int c = 0; c < 16; c++) {
            float d2 = h2[c] - mean;
            vv += d2 * d2;
        }
        vv += __shfl_xor_sync(0xffffffffu, vv, 1);
        vv += __shfl_xor_sync(0xffffffffu, vv, 2);
        float rstd = rsqrtf(vv * (1.0f / 64.0f) + 1e-5f);

        int gbase = token_gaddr(blockIdx.x, row);
#pragma unroll
        for (int q = 0; q < 4; q++) {
            int c = pp * 16 + q * 4;
            float4 xv = *(const float4*)(sm + OFF_X + row * LD + c);
            float4 hv = *(const float4*)(sm + OFF_V + row * LD + c);
            float4 ov;
            ov.x = xv.x + (hv.x - mean) * rstd * s_n2g[c]     + s_n2b[c];
            ov.y = xv.y + (hv.y - mean) * rstd * s_n2g[c + 1] + s_n2b[c + 1];
            ov.z = xv.z + (hv.z - mean) * rstd * s_n2g[c + 2] + s_n2b[c + 2];
            ov.w = xv.w + (hv.w - mean) * rstd * s_n2g[c + 3] + s_n2b[c + 3];
            *(float4*)(out + gbase + c) = ov;
        }
    }
}

// ---------------------------------------------------------------------------
extern "C" void kernel_launch(void* const* d_in, const int* in_sizes, int n_in,
                              void* d_out, int out_size) {
    const float* x      = (const float*)d_in[0];
    const float* qkv_w  = (const float*)d_in[1];
    const float* qkv_b  = (const float*)d_in[2];
    const float* proj_w = (const float*)d_in[3];
    const float* proj_b = (const float*)d_in[4];
    const float* lscale = (const float*)d_in[5];
    const float* cpb_w1 = (const float*)d_in[6];
    const float* cpb_b1 = (const float*)d_in[7];
    const float* cpb_w2 = (const float*)d_in[8];
    const float* n1g    = (const float*)d_in[9];
    const float* n1b    = (const float*)d_in[10];
    const float* n2g    = (const float*)d_in[11];
    const float* n2b    = (const float*)d_in[12];
    const float* fc1_w  = (const float*)d_in[13];
    const float* fc1_b  = (const float*)d_in[14];
    const float* fc2_w  = (const float*)d_in[15];
    const float* fc2_b  = (const float*)d_in[16];
    float* out = (float*)d_out;

    cudaFuncSetAttribute(swin_kernel, cudaFuncAttributeMaxDynamicSharedMemorySize, SMEM_BYTES);

    cpb_kernel<<<196, 128>>>(cpb_w1, cpb_b1, cpb_w2);
    expand_kernel<<<4, 256>>>(lscale);
    wsplit_kernel<<<48, 256>>>(qkv_w, proj_w, fc1_w, fc2_w);
    swin_kernel<<<8192, NTHREADS, SMEM_BYTES>>>(x, qkv_b, proj_b,
                                                n1g, n1b, n2g, n2b,
                                                fc1_b, fc2_b, out);
}

// round 9
// speedup vs baseline: 2.9639x; 1.0933x over previous
#include <cuda_runtime.h>
#include <cuda_bf16.h>
#include <cstdint>
#include <math.h>

// SwinTransformerBlockV2 fused kernel, v6.
// Shift (8,8) multiple of window (4,4) => shift cancels, mask == 0.
// All GEMMs AND attention on tensor cores (m16n8k16 bf16, 2-term hi/lo split).
// v6: attention per (window,head) as warp-level MMA with fragment chaining
// (S C-frag == P A-frag), quad-shuffle softmax, bias preloaded in accumulator,
// V written transposed by the QKV epilogue.

#define NTHREADS 256
#define LD   68
#define LDH2 68

#define OFF_X    0
#define OFF_Q    4352
#define OFF_K    8704
#define OFF_V    13056      // holds V TRANSPOSED: Vt[ch][token], stride LD
#define OFF_ATTH 17408
#define OFF_ATTL 19712
#define OFF_HH   OFF_Q
#define OFF_HL   OFF_K
#define SMEM_FLOATS 22016
#define SMEM_BYTES  (SMEM_FLOATS * 4)

__device__ float g_tab[49 * 4];
__device__ float g_biasf[4 * 256];   // fragment layout: [hh][lane][8]
__device__ float g_scale[4];

// fragment-ready weights (see wsplit_kernel)
__device__ uint4 g_fqkv[3072];
__device__ uint4 g_fproj[1024];
__device__ uint4 g_ffc1[4096];
__device__ uint4 g_ffc2[4096];

// ---------------------------------------------------------------------------
// Setup kernels
// ---------------------------------------------------------------------------
__device__ __forceinline__ float cpb_coord(int d) {
    float t = (8.0f / 3.0f) * (float)d;
    float v = log2f(fabsf(t) + 1.0f) / 3.0f;
    return (t < 0.0f) ? -v : v;
}

__global__ void cpb_kernel(const float* __restrict__ w1, const float* __restrict__ b1,
                           const float* __restrict__ w2) {
    int q = blockIdx.x >> 2;
    int h = blockIdx.x & 3;
    int a = q / 7;
    int b = q % 7;
    float c0 = cpb_coord(a - 3);
    float c1 = cpb_coord(b - 3);
    int tid = threadIdx.x;
    float s = 0.0f;
#pragma unroll
    for (int r = 0; r < 4; r++) {
        int j = tid + r * 128;
        float u = c0 * w1[2 * j] + c1 * w1[2 * j + 1] + b1[j];
        u = fmaxf(u, 0.0f);
        s += u * w2[h * 512 + j];
    }
    __shared__ float red[4];
#pragma unroll
    for (int o = 16; o > 0; o >>= 1) s += __shfl_xor_sync(0xffffffffu, s, o);
    if ((tid & 31) == 0) red[tid >> 5] = s;
    __syncthreads();
    if (tid == 0) g_tab[q * 4 + h] = red[0] + red[1] + red[2] + red[3];
}

// bias in MMA fragment layout: entry (hh, lane, i):
//  i=0..3 -> (r,c) = (g,2t),(g,2t+1),(g+8,2t),(g+8,2t+1)        [s0 frag]
//  i=4..7 -> same with c+8                                       [s1 frag]
__global__ void expand_kernel(const float* __restrict__ ls) {
    int e = blockIdx.x * 256 + threadIdx.x;   // 0..1023
    int hh = e >> 8;
    int lane = (e >> 3) & 31;
    int i = e & 7;
    int g = lane >> 2;
    int t = lane & 3;
    int r = g + ((i & 2) ? 8 : 0);
    int c = 2 * t + (i & 1) + ((i & 4) ? 8 : 0);
    int idx = ((r >> 2) - (c >> 2) + 3) * 7 + ((r & 3) - (c & 3) + 3);
    float v = g_tab[idx * 4 + hh];
    g_biasf[hh * 256 + lane * 8 + i] = 16.0f / (1.0f + expf(-v));
    if (e < 4) g_scale[e] = expf(fminf(ls[e], logf(100.0f)));
}

__device__ __forceinline__ uint32_t pack_split(float x, float y, uint32_t& lo) {
    uint32_t hi;
    asm("cvt.rn.bf16x2.f32 %0, %1, %2;" : "=r"(hi) : "f"(y), "f"(x));
    float hx = __uint_as_float(hi << 16);
    float hy = __uint_as_float(hi & 0xffff0000u);
    asm("cvt.rn.bf16x2.f32 %0, %1, %2;" : "=r"(lo) : "f"(y - hy), "f"(x - hx));
    return hi;
}

__global__ void wsplit_kernel(const float* __restrict__ qkv_w, const float* __restrict__ proj_w,
                              const float* __restrict__ fc1_w, const float* __restrict__ fc2_w) {
    int i = blockIdx.x * 256 + threadIdx.x;
    const float* src;
    uint4* dst;
    int q, K, lgKS;
    if (i < 3072) {
        q = i; src = qkv_w; dst = g_fqkv; K = 64; lgKS = 2;
    } else if (i < 4096) {
        q = i - 3072; src = proj_w; dst = g_fproj; K = 64; lgKS = 2;
    } else if (i < 8192) {
        q = i - 4096; src = fc1_w; dst = g_ffc1; K = 64; lgKS = 2;
    } else if (i < 12288) {
        q = i - 8192; src = fc2_w; dst = g_ffc2; K = 256; lgKS = 4;
    } else {
        return;
    }
    int t  = q & 3;
    int g  = (q >> 2) & 7;
    int ks = (q >> 5) & ((1 << lgKS) - 1);
    int o  = q >> (5 + lgKS);
    int n  = o * 8 + g;
    int p0 = ks * 8 + t;
    int p1 = p0 + 4;
    const float* row = src + n * K;
    uint32_t lo0, lo1;
    uint32_t hi0 = pack_split(row[2 * p0], row[2 * p0 + 1], lo0);
    uint32_t hi1 = pack_split(row[2 * p1], row[2 * p1 + 1], lo1);
    dst[q] = make_uint4(hi0, hi1, lo0, lo1);
}

// ---------------------------------------------------------------------------
// mma helpers
// ---------------------------------------------------------------------------
__device__ __forceinline__ void mma_bf16(float* dd,
        uint32_t a0, uint32_t a1, uint32_t a2, uint32_t a3,
        uint32_t b0, uint32_t b1) {
    asm volatile("mma.sync.aligned.m16n8k16.row.col.f32.bf16.bf16.f32 "
                 "{%0,%1,%2,%3}, {%4,%5,%6,%7}, {%8,%9}, {%0,%1,%2,%3};\n"
                 : "+f"(dd[0]), "+f"(dd[1]), "+f"(dd[2]), "+f"(dd[3])
                 : "r"(a0), "r"(a1), "r"(a2), "r"(a3), "r"(b0), "r"(b1));
}

__device__ __forceinline__ uint32_t split2(float x, float y, uint32_t& lo) {
    return pack_split(x, y, lo);
}

// M2 (two m16 tiles per warp), A = f32 smem tile (stride LD), B direct global frags
template<int NT, int KSTEPS>
__device__ __forceinline__ void gemm2_f32A(const float* A, int mrow,
        const uint4* __restrict__ Bf, int KS_total, int ks0, int o0,
        float (&d)[2][NT][4], int g, int t) {
#pragma unroll
    for (int ks = 0; ks < KSTEPS; ks++) {
        uint32_t ah[2][4], al[2][4];
#pragma unroll
        for (int i2 = 0; i2 < 2; i2++) {
            const float* ap = A + (mrow + i2 * 16 + g) * LD + ks * 16 + 2 * t;
            float2 p0 = *(const float2*)(ap);
            float2 p1 = *(const float2*)(ap + 8 * LD);
            float2 p2 = *(const float2*)(ap + 8);
            float2 p3 = *(const float2*)(ap + 8 * LD + 8);
            ah[i2][0] = split2(p0.x, p0.y, al[i2][0]);
            ah[i2][1] = split2(p1.x, p1.y, al[i2][1]);
            ah[i2][2] = split2(p2.x, p2.y, al[i2][2]);
            ah[i2][3] = split2(p3.x, p3.y, al[i2][3]);
        }
        int base = (ks0 + ks) * 32 + g * 4 + t;
#pragma unroll
        for (int j = 0; j < NT; j++) {
            uint4 b = Bf[(o0 + j) * (KS_total * 32) + base];
#pragma unroll
            for (int i2 = 0; i2 < 2; i2++) {
                mma_bf16(d[i2][j], ah[i2][0], ah[i2][1], ah[i2][2], ah[i2][3], b.x, b.y);
                mma_bf16(d[i2][j], al[i2][0], al[i2][1], al[i2][2], al[i2][3], b.x, b.y);
                mma_bf16(d[i2][j], ah[i2][0], ah[i2][1], ah[i2][2], ah[i2][3], b.z, b.w);
            }
        }
    }
}

// M1 (one m16 tile), A = pre-split bf16 hi/lo u32 smem arrays, B direct global frags
template<int NT, int KSTEPS>
__device__ __forceinline__ void gemm1_splitA(const uint32_t* Ah, const uint32_t* Al,
        int lda2, int mrow,
        const uint4* __restrict__ Bf, int KS_total, int ks0, int o0,
        float (&d)[NT][4], int g, int t) {
#pragma unroll
    for (int ks = 0; ks < KSTEPS; ks++) {
        int ar = (mrow + g) * lda2 + ks * 8 + t;
        uint32_t ah0 = Ah[ar];
        uint32_t ah1 = Ah[ar + 8 * lda2];
        uint32_t ah2 = Ah[ar + 4];
        uint32_t ah3 = Ah[ar + 8 * lda2 + 4];
        uint32_t al0 = Al[ar];
        uint32_t al1 = Al[ar + 8 * lda2];
        uint32_t al2 = Al[ar + 4];
        uint32_t al3 = Al[ar + 8 * lda2 + 4];
        int base = (ks0 + ks) * 32 + g * 4 + t;
#pragma unroll
        for (int j = 0; j < NT; j++) {
            uint4 b = Bf[(o0 + j) * (KS_total * 32) + base];
            mma_bf16(d[j], ah0, ah1, ah2, ah3, b.x, b.y);
            mma_bf16(d[j], al0, al1, al2, al3, b.x, b.y);
            mma_bf16(d[j], ah0, ah1, ah2, ah3, b.z, b.w);
        }
    }
}

__device__ __forceinline__ int token_gaddr(int blk, int lt) {
    int wi = blk * 4 + (lt >> 4);
    int n  = lt & 15;
    int b  = wi >> 12;
    int r  = wi & 4095;
    int wh = r >> 6;
    int ww = r & 63;
    int row = wh * 4 + (n >> 2);
    int col = ww * 4 + (n & 3);
    return ((b * 256 + row) * 256 + col) * 64;
}

// ---------------------------------------------------------------------------
__global__ __launch_bounds__(NTHREADS, 2)
void swin_kernel(const float* __restrict__ x,
                 const float* __restrict__ qkv_b, const float* __restrict__ proj_b,
                 const float* __restrict__ n1g, const float* __restrict__ n1b,
                 const float* __restrict__ n2g, const float* __restrict__ n2b,
                 const float* __restrict__ fc1_b, const float* __restrict__ fc2_b,
                 float* __restrict__ out) {
    extern __shared__ float sm[];
    uint32_t* smu = (uint32_t*)sm;
    __shared__ float s_qkvb[192];
    __shared__ float s_projb[64];
    __shared__ float s_fc1b[256];
    __shared__ float s_fc2b[64];
    __shared__ float s_n1g[64];
    __shared__ float s_n1b[64];
    __shared__ float s_n2g[64];
    __shared__ float s_n2b[64];
    __shared__ float s_scale[4];

    const int tid  = threadIdx.x;
    const int warp = tid >> 5;
    const int lane = tid & 31;
    const int g = lane >> 2;
    const int t = lane & 3;
    // M2 decomposition (QKV, fc1): 2 m-warps x 4 n-warps
    const int mt2 = warp >> 2;
    const int nh4 = warp & 3;
    const int mrow2 = mt2 * 32;
    // M1 decomposition (proj, fc2): 4 m-warps x 2 n-warps
    const int mt1 = warp & 3;
    const int nh1 = warp >> 2;
    const int mrow1 = mt1 * 16;

    // ---- phase 0: params + x tile ----
    if (tid < 192) s_qkvb[tid] = (tid >= 64 && tid < 128) ? 0.0f : qkv_b[tid];
    if (tid < 64) {
        s_projb[tid] = proj_b[tid];
        s_fc2b[tid]  = fc2_b[tid];
        s_n1g[tid] = n1g[tid];
        s_n1b[tid] = n1b[tid];
        s_n2g[tid] = n2g[tid];
        s_n2b[tid] = n2b[tid];
    }
    s_fc1b[tid] = fc1_b[tid];
    if (tid >= 192 && tid < 196) s_scale[tid - 192] = g_scale[tid - 192];

    {
        int lt = tid >> 2;
        int pp = tid & 3;
        int gbase = token_gaddr(blockIdx.x, lt);
        const float4* xp = (const float4*)(x + gbase + pp * 16);
        float4* xd = (float4*)(sm + OFF_X + lt * LD + pp * 16);
#pragma unroll
        for (int i = 0; i < 4; i++) xd[i] = xp[i];
    }
    __syncthreads();

    // ---- phase 1: QKV GEMM (M2); V written TRANSPOSED ----
    {
        float d[2][6][4];
#pragma unroll
        for (int i2 = 0; i2 < 2; i2++)
#pragma unroll
            for (int j = 0; j < 6; j++)
#pragma unroll
                for (int i = 0; i < 4; i++) d[i2][j][i] = 0.0f;
        gemm2_f32A<6, 4>(sm + OFF_X, mrow2, g_fqkv, 4, 0, nh4 * 6, d, g, t);
#pragma unroll
        for (int j = 0; j < 6; j++) {
            int c = nh4 * 48 + 8 * j + 2 * t;
            float b0 = s_qkvb[c];
            float b1 = s_qkvb[c + 1];
            if (c < 128) {
                int col = c & 63;
                float* dst = sm + (c < 64 ? OFF_Q : OFF_K);
#pragma unroll
                for (int i2 = 0; i2 < 2; i2++) {
                    int r = mrow2 + i2 * 16 + g;
                    *(float2*)(dst + r * LD + col)       = make_float2(d[i2][j][0] + b0, d[i2][j][1] + b1);
                    *(float2*)(dst + (r + 8) * LD + col) = make_float2(d[i2][j][2] + b0, d[i2][j][3] + b1);
                }
            } else {
                int col = c - 128;   // V channel -> transposed store Vt[ch][token]
#pragma unroll
                for (int i2 = 0; i2 < 2; i2++) {
                    int r = mrow2 + i2 * 16 + g;
                    sm[OFF_V + col * LD + r]           = d[i2][j][0] + b0;
                    sm[OFF_V + (col + 1) * LD + r]     = d[i2][j][1] + b1;
                    sm[OFF_V + col * LD + r + 8]       = d[i2][j][2] + b0;
                    sm[OFF_V + (col + 1) * LD + r + 8] = d[i2][j][3] + b1;
                }
            }
        }
    }
    __syncthreads();

    // ---- phase 2: attention via tensor cores; one warp per (window,head) ----
    {
#pragma unroll 1
        for (int it = 0; it < 2; it++) {
            int tk = warp * 2 + it;
            int wl = tk >> 2;
            int hh = tk & 3;
            int r0 = wl * 16;

            // Q fragment rows g, g+8; k-pairs 2t, 2t+8 (head-local channels)
            const float* Qb = sm + OFF_Q + (r0 + g) * LD + hh * 16;
            float2 q0 = *(const float2*)(Qb + 2 * t);
            float2 q1 = *(const float2*)(Qb + 2 * t + 8);
            float2 q2 = *(const float2*)(Qb + 8 * LD + 2 * t);
            float2 q3 = *(const float2*)(Qb + 8 * LD + 2 * t + 8);
            float ssA = q0.x * q0.x + q0.y * q0.y + q1.x * q1.x + q1.y * q1.y;
            float ssB = q2.x * q2.x + q2.y * q2.y + q3.x * q3.x + q3.y * q3.y;
            ssA += __shfl_xor_sync(0xffffffffu, ssA, 1);
            ssA += __shfl_xor_sync(0xffffffffu, ssA, 2);
            ssB += __shfl_xor_sync(0xffffffffu, ssB, 1);
            ssB += __shfl_xor_sync(0xffffffffu, ssB, 2);
            float scl = s_scale[hh];
            float iA = scl * rsqrtf(fmaxf(ssA, 1e-24f));
            float iB = scl * rsqrtf(fmaxf(ssB, 1e-24f));
            q0.x *= iA; q0.y *= iA; q1.x *= iA; q1.y *= iA;
            q2.x *= iB; q2.y *= iB; q3.x *= iB; q3.y *= iB;

            // K fragment (same positions)
            const float* Kb = sm + OFF_K + (r0 + g) * LD + hh * 16;
            float2 k0 = *(const float2*)(Kb + 2 * t);
            float2 k1 = *(const float2*)(Kb + 2 * t + 8);
            float2 k2 = *(const float2*)(Kb + 8 * LD + 2 * t);
            float2 k3 = *(const float2*)(Kb + 8 * LD + 2 * t + 8);
            float skA = k0.x * k0.x + k0.y * k0.y + k1.x * k1.x + k1.y * k1.y;
            float skB = k2.x * k2.x + k2.y * k2.y + k3.x * k3.x + k3.y * k3.y;
            skA += __shfl_xor_sync(0xffffffffu, skA, 1);
            skA += __shfl_xor_sync(0xffffffffu, skA, 2);
            skB += __shfl_xor_sync(0xffffffffu, skB, 1);
            skB += __shfl_xor_sync(0xffffffffu, skB, 2);
            float jA = rsqrtf(fmaxf(skA, 1e-24f));
            float jB = rsqrtf(fmaxf(skB, 1e-24f));
            k0.x *= jA; k0.y *= jA; k1.x *= jA; k1.y *= jA;
            k2.x *= jB; k2.y *= jB; k3.x *= jB; k3.y *= jB;

            // split
            uint32_t ql0, ql1, ql2, ql3, kl0, kl1, kl2, kl3;
            uint32_t qh0 = split2(q0.x, q0.y, ql0);
            uint32_t qh1 = split2(q1.x, q1.y, ql1);
            uint32_t qh2 = split2(q2.x, q2.y, ql2);
            uint32_t qh3 = split2(q3.x, q3.y, ql3);
            uint32_t kh0 = split2(k0.x, k0.y, kl0);
            uint32_t kh1 = split2(k1.x, k1.y, kl1);
            uint32_t kh2 = split2(k2.x, k2.y, kl2);
            uint32_t kh3 = split2(k3.x, k3.y, kl3);

            // S = bias (preloaded into accumulator) + Qn Kn^T
            const float4* bf = (const float4*)(g_biasf + hh * 256 + lane * 8);
            float4 bb0 = bf[0];
            float4 bb1 = bf[1];
            float s0[4] = {bb0.x, bb0.y, bb0.z, bb0.w};
            float s1[4] = {bb1.x, bb1.y, bb1.z, bb1.w};
            // a-frag order: (g,2t), (g+8,2t), (g,2t+8), (g+8,2t+8)
            mma_bf16(s0, qh0, qh2, qh1, qh3, kh0, kh1);
            mma_bf16(s0, ql0, ql2, ql1, ql3, kh0, kh1);
            mma_bf16(s0, qh0, qh2, qh1, qh3, kl0, kl1);
            mma_bf16(s1, qh0, qh2, qh1, qh3, kh2, kh3);
            mma_bf16(s1, ql0, ql2, ql1, ql3, kh2, kh3);
            mma_bf16(s1, qh0, qh2, qh1, qh3, kl2, kl3);

            // softmax rows g (s0[0],s0[1],s1[0],s1[1]) and g+8 (s0[2],s0[3],s1[2],s1[3])
            float mA = fmaxf(fmaxf(s0[0], s0[1]), fmaxf(s1[0], s1[1]));
            float mB = fmaxf(fmaxf(s0[2], s0[3]), fmaxf(s1[2], s1[3]));
            mA = fmaxf(mA, __shfl_xor_sync(0xffffffffu, mA, 1));
            mA = fmaxf(mA, __shfl_xor_sync(0xffffffffu, mA, 2));
            mB = fmaxf(mB, __shfl_xor_sync(0xffffffffu, mB, 1));
            mB = fmaxf(mB, __shfl_xor_sync(0xffffffffu, mB, 2));
            s0[0] = __expf(s0[0] - mA);
            s0[1] = __expf(s0[1] - mA);
            s1[0] = __expf(s1[0] - mA);
            s1[1] = __expf(s1[1] - mA);
            s0[2] = __expf(s0[2] - mB);
            s0[3] = __expf(s0[3] - mB);
            s1[2] = __expf(s1[2] - mB);
            s1[3] = __expf(s1[3] - mB);
            float suA = s0[0] + s0[1] + s1[0] + s1[1];
            float suB = s0[2] + s0[3] + s1[2] + s1[3];
            suA += __shfl_xor_sync(0xffffffffu, suA, 1);
            suA += __shfl_xor_sync(0xffffffffu, suA, 2);
            suB += __shfl_xor_sync(0xffffffffu, suB, 1);
            suB += __shfl_xor_sync(0xffffffffu, suB, 2);
            float ivA = 1.0f / suA;
            float ivB = 1.0f / suB;

            // P fragment (chained from S): a0=(g,k2t)=s0[0..1], a1=(g+8,k2t)=s0[2..3],
            // a2=(g,k2t+8)=s1[0..1], a3=(g+8,k2t+8)=s1[2..3]
            uint32_t pl0, pl1, pl2, pl3;
            uint32_t ph0 = split2(s0[0], s0[1], pl0);
            uint32_t ph1 = split2(s0[2], s0[3], pl1);
            uint32_t ph2 = split2(s1[0], s1[1], pl2);
            uint32_t ph3 = split2(s1[2], s1[3], pl3);

            // V b-frags from Vt: n-half0 d = hh*16+g, n-half1 d+8
            const float* Vb = sm + OFF_V + (hh * 16 + g) * LD + r0;
            float2 v0 = *(const float2*)(Vb + 2 * t);
            float2 v1 = *(const float2*)(Vb + 2 * t + 8);
            float2 v2 = *(const float2*)(Vb + 8 * LD + 2 * t);
            float2 v3 = *(const float2*)(Vb + 8 * LD + 2 * t + 8);
            uint32_t vl0, vl1, vl2, vl3;
            uint32_t vh0 = split2(v0.x, v0.y, vl0);
            uint32_t vh1 = split2(v1.x, v1.y, vl1);
            uint32_t vh2 = split2(v2.x, v2.y, vl2);
            uint32_t vh3 = split2(v3.x, v3.y, vl3);

            float o0[4] = {0.0f, 0.0f, 0.0f, 0.0f};
            float o1[4] = {0.0f, 0.0f, 0.0f, 0.0f};
            mma_bf16(o0, ph0, ph1, ph2, ph3, vh0, vh1);
            mma_bf16(o0, pl0, pl1, pl2, pl3, vh0, vh1);
            mma_bf16(o0, ph0, ph1, ph2, ph3, vl0, vl1);
            mma_bf16(o1, ph0, ph1, ph2, ph3, vh2, vh3);
            mma_bf16(o1, pl0, pl1, pl2, pl3, vh2, vh3);
            mma_bf16(o1, ph0, ph1, ph2, ph3, vl2, vl3);

            // scale rows by 1/sum, split, store to ATT layout [64][36]
            o0[0] *= ivA; o0[1] *= ivA; o1[0] *= ivA; o1[1] *= ivA;
            o0[2] *= ivB; o0[3] *= ivB; o1[2] *= ivB; o1[3] *= ivB;
            uint32_t zl0, zl1, zl2, zl3;
            uint32_t zh0 = split2(o0[0], o0[1], zl0);   // row g,   cols 2t,2t+1
            uint32_t zh1 = split2(o1[0], o1[1], zl1);   // row g,   cols 8+2t
            uint32_t zh2 = split2(o0[2], o0[3], zl2);   // row g+8, cols 2t
            uint32_t zh3 = split2(o1[2], o1[3], zl3);   // row g+8, cols 8+2t
            int rw = (r0 + g) * 36 + hh * 8;
            smu[OFF_ATTH + rw + t]            = zh0;
            smu[OFF_ATTH + rw + t + 4]        = zh1;
            smu[OFF_ATTH + rw + 8 * 36 + t]     = zh2;
            smu[OFF_ATTH + rw + 8 * 36 + t + 4] = zh3;
            smu[OFF_ATTL + rw + t]            = zl0;
            smu[OFF_ATTL + rw + t + 4]        = zl1;
            smu[OFF_ATTL + rw + 8 * 36 + t]     = zl2;
            smu[OFF_ATTL + rw + 8 * 36 + t + 4] = zl3;
        }
    }
    __syncthreads();

    // ---- phase 3: proj GEMM (M1, A = pre-split ATT) -> 'a' into K buffer ----
    {
        float d[4][4];
#pragma unroll
        for (int j = 0; j < 4; j++)
#pragma unroll
            for (int i = 0; i < 4; i++) d[j][i] = 0.0f;
        gemm1_splitA<4, 4>(smu + OFF_ATTH, smu + OFF_ATTL, 36, mrow1,
                           g_fproj, 4, 0, nh1 * 4, d, g, t);
#pragma unroll
        for (int j = 0; j < 4; j++) {
            int c = nh1 * 32 + 8 * j + 2 * t;
            float b0 = s_projb[c];
            float b1 = s_projb[c + 1];
            *(float2*)(sm + OFF_K + (mrow1 + g) * LD + c)     = make_float2(d[j][0] + b0, d[j][1] + b1);
            *(float2*)(sm + OFF_K + (mrow1 + g + 8) * LD + c) = make_float2(d[j][2] + b0, d[j][3] + b1);
        }
    }
    __syncthreads();

    // ---- phase 4: LN1 + residual in place over x (4 threads per row) ----
    {
        int row = tid >> 2;
        int sub = tid & 3;
        const float* a = sm + OFF_K + row * LD + sub * 16;
        float s = 0.0f;
#pragma unroll
        for (int c = 0; c < 16; c++) s += a[c];
        s += __shfl_xor_sync(0xffffffffu, s, 1);
        s += __shfl_xor_sync(0xffffffffu, s, 2);
        float mean = s * (1.0f / 64.0f);
        float vv = 0.0f;
#pragma unroll
        for (int c = 0; c < 16; c++) {
            float d2 = a[c] - mean;
            vv += d2 * d2;
        }
        vv += __shfl_xor_sync(0xffffffffu, vv, 1);
        vv += __shfl_xor_sync(0xffffffffu, vv, 2);
        float rstd = rsqrtf(vv * (1.0f / 64.0f) + 1e-5f);
        float* xr = sm + OFF_X + row * LD + sub * 16;
        const float* gg = s_n1g + sub * 16;
        const float* bbv = s_n1b + sub * 16;
#pragma unroll
        for (int c = 0; c < 16; c++) {
            xr[c] = xr[c] + (a[c] - mean) * rstd * gg[c] + bbv[c];
        }
    }
    __syncthreads();

    // ---- phase 5: MLP in two 128-wide halves ----
    float dacc[4][4];
#pragma unroll
    for (int j = 0; j < 4; j++)
#pragma unroll
        for (int i = 0; i < 4; i++) dacc[j][i] = 0.0f;

#pragma unroll 1
    for (int kh = 0; kh < 2; kh++) {
        {
            float d[2][4][4];
#pragma unroll
            for (int i2 = 0; i2 < 2; i2++)
#pragma unroll
                for (int j = 0; j < 4; j++)
#pragma unroll
                    for (int i = 0; i < 4; i++) d[i2][j][i] = 0.0f;
            gemm2_f32A<4, 4>(sm + OFF_X, mrow2, g_ffc1, 4, 0, kh * 16 + nh4 * 4, d, g, t);
#pragma unroll
            for (int j = 0; j < 4; j++) {
                int c = nh4 * 32 + 8 * j + 2 * t;
                float b0 = s_fc1b[kh * 128 + c];
                float b1 = s_fc1b[kh * 128 + c + 1];
                int col2 = nh4 * 16 + 4 * j + t;
#pragma unroll
                for (int i2 = 0; i2 < 2; i2++) {
                    float v0 = d[i2][j][0] + b0;
                    float v1 = d[i2][j][1] + b1;
                    float v2 = d[i2][j][2] + b0;
                    float v3 = d[i2][j][3] + b1;
                    v0 = v0 * 0.5f * (1.0f + erff(v0 * 0.70710678118654752f));
                    v1 = v1 * 0.5f * (1.0f + erff(v1 * 0.70710678118654752f));
                    v2 = v2 * 0.5f * (1.0f + erff(v2 * 0.70710678118654752f));
                    v3 = v3 * 0.5f * (1.0f + erff(v3 * 0.70710678118654752f));
                    int r = mrow2 + i2 * 16 + g;
                    uint32_t lo0, lo1;
                    uint32_t hi0 = split2(v0, v1, lo0);
                    uint32_t hi1 = split2(v2, v3, lo1);
                    smu[OFF_HH + r * LDH2 + col2]       = hi0;
                    smu[OFF_HL + r * LDH2 + col2]       = lo0;
                    smu[OFF_HH + (r + 8) * LDH2 + col2] = hi1;
                    smu[OFF_HL + (r + 8) * LDH2 + col2] = lo1;
                }
            }
        }
        __syncthreads();
        gemm1_splitA<4, 8>(smu + OFF_HH, smu + OFF_HL, LDH2, mrow1,
                           g_ffc2, 16, kh * 8, nh1 * 4, dacc, g, t);
        __syncthreads();
    }

    // h2 -> V region (Vt dead)
#pragma unroll
    for (int j = 0; j < 4; j++) {
        int c = nh1 * 32 + 8 * j + 2 * t;
        float b0 = s_fc2b[c];
        float b1 = s_fc2b[c + 1];
        *(float2*)(sm + OFF_V + (mrow1 + g) * LD + c)     = make_float2(dacc[j][0] + b0, dacc[j][1] + b1);
        *(float2*)(sm + OFF_V + (mrow1 + g + 8) * LD + c) = make_float2(dacc[j][2] + b0, dacc[j][3] + b1);
    }
    __syncthreads();

    // ---- phase 6: LN2 fused with final residual + store ----
    {
        int row = tid >> 2;
        int pp = tid & 3;
        const float* h2 = sm + OFF_V + row * LD + pp * 16;
        float s = 0.0f;
#pragma unroll
        for (int c = 0; c < 16; c++) s += h2[c];
        s += __shfl_xor_sync(0xffffffffu, s, 1);
        s += __shfl_xor_sync(0xffffffffu, s, 2);
        float mean = s * (1.0f / 64.0f);
        float vv = 0.0f;
#pragma unroll
        for (int c = 0; c < 16; c++) {
            float d2 = h2[c] - mean;
            vv += d2 * d2;
        }
        vv += __shfl_xor_sync(0xffffffffu, vv, 1);
        vv += __shfl_xor_sync(0xffffffffu, vv, 2);
        float rstd = rsqrtf(vv * (1.0f / 64.0f) + 1e-5f);

        int gbase = token_gaddr(blockIdx.x, row);
#pragma unroll
        for (int q = 0; q < 4; q++) {
            int c = pp * 16 + q * 4;
            float4 xv = *(const float4*)(sm + OFF_X + row * LD + c);
            float4 hv = *(const float4*)(sm + OFF_V + row * LD + c);
            float4 ov;
            ov.x = xv.x + (hv.x - mean) * rstd * s_n2g[c]     + s_n2b[c];
            ov.y = xv.y + (hv.y - mean) * rstd * s_n2g[c + 1] + s_n2b[c + 1];
            ov.z = xv.z + (hv.z - mean) * rstd * s_n2g[c + 2] + s_n2b[c + 2];
            ov.w = xv.w + (hv.w - mean) * rstd * s_n2g[c + 3] + s_n2b[c + 3];
            *(float4*)(out + gbase + c) = ov;
        }
    }
}

// ---------------------------------------------------------------------------
extern "C" void kernel_launch(void* const* d_in, const int* in_sizes, int n_in,
                              void* d_out, int out_size) {
    const float* x      = (const float*)d_in[0];
    const float* qkv_w  = (const float*)d_in[1];
    const float* qkv_b  = (const float*)d_in[2];
    const float* proj_w = (const float*)d_in[3];
    const float* proj_b = (const float*)d_in[4];
    const float* lscale = (const float*)d_in[5];
    const float* cpb_w1 = (const float*)d_in[6];
    const float* cpb_b1 = (const float*)d_in[7];
    const float* cpb_w2 = (const float*)d_in[8];
    const float* n1g    = (const float*)d_in[9];
    const float* n1b    = (const float*)d_in[10];
    const float* n2g    = (const float*)d_in[11];
    const float* n2b    = (const float*)d_in[12];
    const float* fc1_w  = (const float*)d_in[13];
    const float* fc1_b  = (const float*)d_in[14];
    const float* fc2_w  = (const float*)d_in[15];
    const float* fc2_b  = (const float*)d_in[16];
    float* out = (float*)d_out;

    cudaFuncSetAttribute(swin_kernel, cudaFuncAttributeMaxDynamicSharedMemorySize, SMEM_BYTES);

    cpb_kernel<<<196, 128>>>(cpb_w1, cpb_b1, cpb_w2);
    expand_kernel<<<4, 256>>>(lscale);
    wsplit_kernel<<<48, 256>>>(qkv_w, proj_w, fc1_w, fc2_w);
    swin_kernel<<<8192, NTHREADS, SMEM_BYTES>>>(x, qkv_b, proj_b,
                                                n1g, n1b, n2g, n2b,
                                                fc1_b, fc2_b, out);
}

// round 10
// speedup vs baseline: 3.0088x; 1.0151x over previous
#include <cuda_runtime.h>
#include <cuda_bf16.h>
#include <cstdint>
#include <math.h>

// SwinTransformerBlockV2 fused kernel, v7.
// Shift (8,8) multiple of window (4,4) => shift cancels, mask == 0.
// All GEMMs AND attention on tensor cores (m16n8k16 bf16, 2-term hi/lo split).
// v7: attention O-fragments chained DIRECTLY into proj MMAs (no ATT smem
// round-trip, no proj A-loads; partial-C buffers summed in LN1); activations
// pre-split once per producer (X at load, x1 in LN1) so all GEMM A-operands
// are pure LDS.32 loads.

#define NTHREADS 256
#define LD   68
#define LDH2 68   // u32 stride for H split (64 pairs + pad)

#define OFF_X    0          // f32 [64][68] x -> x1 in place
#define OFF_Q    4352       // f32 q; then bufA (proj partial, even warps); then HH
#define OFF_K    8704       // f32 k; then bufB (odd warps); then HL
#define OFF_V    13056      // f32 Vt[ch][token]; then h2
#define OFF_XH   17408      // u32 [64][36] x split hi -> x1 split hi
#define OFF_XL   19712      // u32 [64][36] x split lo -> x1 split lo
#define OFF_HH   OFF_Q      // u32 [64][68] fc1+gelu split hi
#define OFF_HL   OFF_K
#define SMEM_FLOATS 22016
#define SMEM_BYTES  (SMEM_FLOATS * 4)

__device__ float g_tab[49 * 4];
__device__ float g_biasf[4 * 256];   // fragment layout: [hh][lane][8]
__device__ float g_scale[4];

// fragment-ready weights (see wsplit_kernel)
__device__ uint4 g_fqkv[3072];
__device__ uint4 g_fproj[1024];
__device__ uint4 g_ffc1[4096];
__device__ uint4 g_ffc2[4096];

// ---------------------------------------------------------------------------
// Setup kernels
// ---------------------------------------------------------------------------
__device__ __forceinline__ float cpb_coord(int d) {
    float t = (8.0f / 3.0f) * (float)d;
    float v = log2f(fabsf(t) + 1.0f) / 3.0f;
    return (t < 0.0f) ? -v : v;
}

__global__ void cpb_kernel(const float* __restrict__ w1, const float* __restrict__ b1,
                           const float* __restrict__ w2) {
    int q = blockIdx.x >> 2;
    int h = blockIdx.x & 3;
    int a = q / 7;
    int b = q % 7;
    float c0 = cpb_coord(a - 3);
    float c1 = cpb_coord(b - 3);
    int tid = threadIdx.x;
    float s = 0.0f;
#pragma unroll
    for (int r = 0; r < 4; r++) {
        int j = tid + r * 128;
        float u = c0 * w1[2 * j] + c1 * w1[2 * j + 1] + b1[j];
        u = fmaxf(u, 0.0f);
        s += u * w2[h * 512 + j];
    }
    __shared__ float red[4];
#pragma unroll
    for (int o = 16; o > 0; o >>= 1) s += __shfl_xor_sync(0xffffffffu, s, o);
    if ((tid & 31) == 0) red[tid >> 5] = s;
    __syncthreads();
    if (tid == 0) g_tab[q * 4 + h] = red[0] + red[1] + red[2] + red[3];
}

__global__ void expand_kernel(const float* __restrict__ ls) {
    int e = blockIdx.x * 256 + threadIdx.x;   // 0..1023
    int hh = e >> 8;
    int lane = (e >> 3) & 31;
    int i = e & 7;
    int g = lane >> 2;
    int t = lane & 3;
    int r = g + ((i & 2) ? 8 : 0);
    int c = 2 * t + (i & 1) + ((i & 4) ? 8 : 0);
    int idx = ((r >> 2) - (c >> 2) + 3) * 7 + ((r & 3) - (c & 3) + 3);
    float v = g_tab[idx * 4 + hh];
    g_biasf[hh * 256 + lane * 8 + i] = 16.0f / (1.0f + expf(-v));
    if (e < 4) g_scale[e] = expf(fminf(ls[e], logf(100.0f)));
}

__device__ __forceinline__ uint32_t pack_split(float x, float y, uint32_t& lo) {
    uint32_t hi;
    asm("cvt.rn.bf16x2.f32 %0, %1, %2;" : "=r"(hi) : "f"(y), "f"(x));
    float hx = __uint_as_float(hi << 16);
    float hy = __uint_as_float(hi & 0xffff0000u);
    asm("cvt.rn.bf16x2.f32 %0, %1, %2;" : "=r"(lo) : "f"(y - hy), "f"(x - hx));
    return hi;
}

__global__ void wsplit_kernel(const float* __restrict__ qkv_w, const float* __restrict__ proj_w,
                              const float* __restrict__ fc1_w, const float* __restrict__ fc2_w) {
    int i = blockIdx.x * 256 + threadIdx.x;
    const float* src;
    uint4* dst;
    int q, K, lgKS;
    if (i < 3072) {
        q = i; src = qkv_w; dst = g_fqkv; K = 64; lgKS = 2;
    } else if (i < 4096) {
        q = i - 3072; src = proj_w; dst = g_fproj; K = 64; lgKS = 2;
    } else if (i < 8192) {
        q = i - 4096; src = fc1_w; dst = g_ffc1; K = 64; lgKS = 2;
    } else if (i < 12288) {
        q = i - 8192; src = fc2_w; dst = g_ffc2; K = 256; lgKS = 4;
    } else {
        return;
    }
    int t  = q & 3;
    int g  = (q >> 2) & 7;
    int ks = (q >> 5) & ((1 << lgKS) - 1);
    int o  = q >> (5 + lgKS);
    int n  = o * 8 + g;
    int p0 = ks * 8 + t;
    int p1 = p0 + 4;
    const float* row = src + n * K;
    uint32_t lo0, lo1;
    uint32_t hi0 = pack_split(row[2 * p0], row[2 * p0 + 1], lo0);
    uint32_t hi1 = pack_split(row[2 * p1], row[2 * p1 + 1], lo1);
    dst[q] = make_uint4(hi0, hi1, lo0, lo1);
}

// ---------------------------------------------------------------------------
// mma helpers
// ---------------------------------------------------------------------------
__device__ __forceinline__ void mma_bf16(float* dd,
        uint32_t a0, uint32_t a1, uint32_t a2, uint32_t a3,
        uint32_t b0, uint32_t b1) {
    asm volatile("mma.sync.aligned.m16n8k16.row.col.f32.bf16.bf16.f32 "
                 "{%0,%1,%2,%3}, {%4,%5,%6,%7}, {%8,%9}, {%0,%1,%2,%3};\n"
                 : "+f"(dd[0]), "+f"(dd[1]), "+f"(dd[2]), "+f"(dd[3])
                 : "r"(a0), "r"(a1), "r"(a2), "r"(a3), "r"(b0), "r"(b1));
}

__device__ __forceinline__ uint32_t split2(float x, float y, uint32_t& lo) {
    return pack_split(x, y, lo);
}

// M2 (two m16 tiles per warp), A = pre-split hi/lo u32 smem (stride 36)
template<int NT, int KSTEPS>
__device__ __forceinline__ void gemm2_splitA(const uint32_t* Ah, const uint32_t* Al,
        int mrow, const uint4* __restrict__ Bf, int KS_total, int ks0, int o0,
        float (&d)[2][NT][4], int g, int t) {
#pragma unroll
    for (int ks = 0; ks < KSTEPS; ks++) {
        uint32_t ah[2][4], al[2][4];
#pragma unroll
        for (int i2 = 0; i2 < 2; i2++) {
            int ar = (mrow + i2 * 16 + g) * 36 + ks * 8 + t;
            ah[i2][0] = Ah[ar];
            ah[i2][1] = Ah[ar + 8 * 36];
            ah[i2][2] = Ah[ar + 4];
            ah[i2][3] = Ah[ar + 8 * 36 + 4];
            al[i2][0] = Al[ar];
            al[i2][1] = Al[ar + 8 * 36];
            al[i2][2] = Al[ar + 4];
            al[i2][3] = Al[ar + 8 * 36 + 4];
        }
        int base = (ks0 + ks) * 32 + g * 4 + t;
#pragma unroll
        for (int j = 0; j < NT; j++) {
            uint4 b = Bf[(o0 + j) * (KS_total * 32) + base];
#pragma unroll
            for (int i2 = 0; i2 < 2; i2++) {
                mma_bf16(d[i2][j], ah[i2][0], ah[i2][1], ah[i2][2], ah[i2][3], b.x, b.y);
                mma_bf16(d[i2][j], al[i2][0], al[i2][1], al[i2][2], al[i2][3], b.x, b.y);
                mma_bf16(d[i2][j], ah[i2][0], ah[i2][1], ah[i2][2], ah[i2][3], b.z, b.w);
            }
        }
    }
}

// M1 (one m16 tile), A = pre-split hi/lo u32 smem arrays (stride lda2)
template<int NT, int KSTEPS>
__device__ __forceinline__ void gemm1_splitA(const uint32_t* Ah, const uint32_t* Al,
        int lda2, int mrow,
        const uint4* __restrict__ Bf, int KS_total, int ks0, int o0,
        float (&d)[NT][4], int g, int t) {
#pragma unroll
    for (int ks = 0; ks < KSTEPS; ks++) {
        int ar = (mrow + g) * lda2 + ks * 8 + t;
        uint32_t ah0 = Ah[ar];
        uint32_t ah1 = Ah[ar + 8 * lda2];
        uint32_t ah2 = Ah[ar + 4];
        uint32_t ah3 = Ah[ar + 8 * lda2 + 4];
        uint32_t al0 = Al[ar];
        uint32_t al1 = Al[ar + 8 * lda2];
        uint32_t al2 = Al[ar + 4];
        uint32_t al3 = Al[ar + 8 * lda2 + 4];
        int base = (ks0 + ks) * 32 + g * 4 + t;
#pragma unroll
        for (int j = 0; j < NT; j++) {
            uint4 b = Bf[(o0 + j) * (KS_total * 32) + base];
            mma_bf16(d[j], ah0, ah1, ah2, ah3, b.x, b.y);
            mma_bf16(d[j], al0, al1, al2, al3, b.x, b.y);
            mma_bf16(d[j], ah0, ah1, ah2, ah3, b.z, b.w);
        }
    }
}

__device__ __forceinline__ int token_gaddr(int blk, int lt) {
    int wi = blk * 4 + (lt >> 4);
    int n  = lt & 15;
    int b  = wi >> 12;
    int r  = wi & 4095;
    int wh = r >> 6;
    int ww = r & 63;
    int row = wh * 4 + (n >> 2);
    int col = ww * 4 + (n & 3);
    return ((b * 256 + row) * 256 + col) * 64;
}

// ---------------------------------------------------------------------------
__global__ __launch_bounds__(NTHREADS, 2)
void swin_kernel(const float* __restrict__ x,
                 const float* __restrict__ qkv_b, const float* __restrict__ proj_b,
                 const float* __restrict__ n1g, const float* __restrict__ n1b,
                 const float* __restrict__ n2g, const float* __restrict__ n2b,
                 const float* __restrict__ fc1_b, const float* __restrict__ fc2_b,
                 float* __restrict__ out) {
    extern __shared__ float sm[];
    uint32_t* smu = (uint32_t*)sm;
    __shared__ float s_qkvb[192];
    __shared__ float s_projb[64];
    __shared__ float s_fc1b[256];
    __shared__ float s_fc2b[64];
    __shared__ float s_n1g[64];
    __shared__ float s_n1b[64];
    __shared__ float s_n2g[64];
    __shared__ float s_n2b[64];
    __shared__ float s_scale[4];

    const int tid  = threadIdx.x;
    const int warp = tid >> 5;
    const int lane = tid & 31;
    const int g = lane >> 2;
    const int t = lane & 3;
    // M2 decomposition (QKV, fc1): 2 m-warps x 4 n-warps
    const int mt2 = warp >> 2;
    const int nh4 = warp & 3;
    const int mrow2 = mt2 * 32;
    // M1 decomposition (fc2): 4 m-warps x 2 n-warps
    const int mt1 = warp & 3;
    const int nh1 = warp >> 2;
    const int mrow1 = mt1 * 16;

    // ---- phase 0: params + x tile (f32 + split) ----
    if (tid < 192) s_qkvb[tid] = (tid >= 64 && tid < 128) ? 0.0f : qkv_b[tid];
    if (tid < 64) {
        s_projb[tid] = proj_b[tid];
        s_fc2b[tid]  = fc2_b[tid];
        s_n1g[tid] = n1g[tid];
        s_n1b[tid] = n1b[tid];
        s_n2g[tid] = n2g[tid];
        s_n2b[tid] = n2b[tid];
    }
    s_fc1b[tid] = fc1_b[tid];
    if (tid >= 192 && tid < 196) s_scale[tid - 192] = g_scale[tid - 192];

    {
        int lt = tid >> 2;
        int pp = tid & 3;
        int gbase = token_gaddr(blockIdx.x, lt);
        const float4* xp = (const float4*)(x + gbase + pp * 16);
        float4* xd = (float4*)(sm + OFF_X + lt * LD + pp * 16);
        uint32_t* xh = smu + OFF_XH + lt * 36 + pp * 8;
        uint32_t* xl = smu + OFF_XL + lt * 36 + pp * 8;
#pragma unroll
        for (int i = 0; i < 4; i++) {
            float4 v4 = xp[i];
            xd[i] = v4;
            uint32_t lo0, lo1;
            uint32_t hi0 = split2(v4.x, v4.y, lo0);
            uint32_t hi1 = split2(v4.z, v4.w, lo1);
            xh[2 * i] = hi0;
            xh[2 * i + 1] = hi1;
            xl[2 * i] = lo0;
            xl[2 * i + 1] = lo1;
        }
    }
    __syncthreads();

    // ---- phase 1: QKV GEMM (M2, pre-split A); V written TRANSPOSED ----
    {
        float d[2][6][4];
#pragma unroll
        for (int i2 = 0; i2 < 2; i2++)
#pragma unroll
            for (int j = 0; j < 6; j++)
#pragma unroll
                for (int i = 0; i < 4; i++) d[i2][j][i] = 0.0f;
        gemm2_splitA<6, 4>(smu + OFF_XH, smu + OFF_XL, mrow2, g_fqkv, 4, 0, nh4 * 6, d, g, t);
#pragma unroll
        for (int j = 0; j < 6; j++) {
            int c = nh4 * 48 + 8 * j + 2 * t;
            float b0 = s_qkvb[c];
            float b1 = s_qkvb[c + 1];
            if (c < 128) {
                int col = c & 63;
                float* dst = sm + (c < 64 ? OFF_Q : OFF_K);
#pragma unroll
                for (int i2 = 0; i2 < 2; i2++) {
                    int r = mrow2 + i2 * 16 + g;
                    *(float2*)(dst + r * LD + col)       = make_float2(d[i2][j][0] + b0, d[i2][j][1] + b1);
                    *(float2*)(dst + (r + 8) * LD + col) = make_float2(d[i2][j][2] + b0, d[i2][j][3] + b1);
                }
            } else {
                int col = c - 128;
#pragma unroll
                for (int i2 = 0; i2 < 2; i2++) {
                    int r = mrow2 + i2 * 16 + g;
                    sm[OFF_V + col * LD + r]           = d[i2][j][0] + b0;
                    sm[OFF_V + (col + 1) * LD + r]     = d[i2][j][1] + b1;
                    sm[OFF_V + col * LD + r + 8]       = d[i2][j][2] + b0;
                    sm[OFF_V + (col + 1) * LD + r + 8] = d[i2][j][3] + b1;
                }
            }
        }
    }
    __syncthreads();

    // ---- phase 2: attention + chained proj partials ----
    // warp w: rows wl = w>>1, heads hh in {2(w&1), 2(w&1)+1}
    {
        float cacc[8][4];
        bool wbias = ((warp & 1) == 0);
#pragma unroll
        for (int j = 0; j < 8; j++) {
            float b0 = wbias ? s_projb[8 * j + 2 * t] : 0.0f;
            float b1 = wbias ? s_projb[8 * j + 2 * t + 1] : 0.0f;
            cacc[j][0] = b0;
            cacc[j][1] = b1;
            cacc[j][2] = b0;
            cacc[j][3] = b1;
        }
        int wl = warp >> 1;
        int r0 = wl * 16;

#pragma unroll 1
        for (int it = 0; it < 2; it++) {
            int hh = (warp & 1) * 2 + it;

            const float* Qb = sm + OFF_Q + (r0 + g) * LD + hh * 16;
            float2 q0 = *(const float2*)(Qb + 2 * t);
            float2 q1 = *(const float2*)(Qb + 2 * t + 8);
            float2 q2 = *(const float2*)(Qb + 8 * LD + 2 * t);
            float2 q3 = *(const float2*)(Qb + 8 * LD + 2 * t + 8);
            float ssA = q0.x * q0.x + q0.y * q0.y + q1.x * q1.x + q1.y * q1.y;
            float ssB = q2.x * q2.x + q2.y * q2.y + q3.x * q3.x + q3.y * q3.y;
            ssA += __shfl_xor_sync(0xffffffffu, ssA, 1);
            ssA += __shfl_xor_sync(0xffffffffu, ssA, 2);
            ssB += __shfl_xor_sync(0xffffffffu, ssB, 1);
            ssB += __shfl_xor_sync(0xffffffffu, ssB, 2);
            float scl = s_scale[hh];
            float iA = scl * rsqrtf(fmaxf(ssA, 1e-24f));
            float iB = scl * rsqrtf(fmaxf(ssB, 1e-24f));
            q0.x *= iA; q0.y *= iA; q1.x *= iA; q1.y *= iA;
            q2.x *= iB; q2.y *= iB; q3.x *= iB; q3.y *= iB;

            const float* Kb = sm + OFF_K + (r0 + g) * LD + hh * 16;
            float2 k0 = *(const float2*)(Kb + 2 * t);
            float2 k1 = *(const float2*)(Kb + 2 * t + 8);
            float2 k2 = *(const float2*)(Kb + 8 * LD + 2 * t);
            float2 k3 = *(const float2*)(Kb + 8 * LD + 2 * t + 8);
            float skA = k0.x * k0.x + k0.y * k0.y + k1.x * k1.x + k1.y * k1.y;
            float skB = k2.x * k2.x + k2.y * k2.y + k3.x * k3.x + k3.y * k3.y;
            skA += __shfl_xor_sync(0xffffffffu, skA, 1);
            skA += __shfl_xor_sync(0xffffffffu, skA, 2);
            skB += __shfl_xor_sync(0xffffffffu, skB, 1);
            skB += __shfl_xor_sync(0xffffffffu, skB, 2);
            float jA = rsqrtf(fmaxf(skA, 1e-24f));
            float jB = rsqrtf(fmaxf(skB, 1e-24f));
            k0.x *= jA; k0.y *= jA; k1.x *= jA; k1.y *= jA;
            k2.x *= jB; k2.y *= jB; k3.x *= jB; k3.y *= jB;

            uint32_t ql0, ql1, ql2, ql3, kl0, kl1, kl2, kl3;
            uint32_t qh0 = split2(q0.x, q0.y, ql0);
            uint32_t qh1 = split2(q1.x, q1.y, ql1);
            uint32_t qh2 = split2(q2.x, q2.y, ql2);
            uint32_t qh3 = split2(q3.x, q3.y, ql3);
            uint32_t kh0 = split2(k0.x, k0.y, kl0);
            uint32_t kh1 = split2(k1.x, k1.y, kl1);
            uint32_t kh2 = split2(k2.x, k2.y, kl2);
            uint32_t kh3 = split2(k3.x, k3.y, kl3);

            const float4* bf = (const float4*)(g_biasf + hh * 256 + lane * 8);
            float4 bb0 = bf[0];
            float4 bb1 = bf[1];
            float s0[4] = {bb0.x, bb0.y, bb0.z, bb0.w};
            float s1[4] = {bb1.x, bb1.y, bb1.z, bb1.w};
            mma_bf16(s0, qh0, qh2, qh1, qh3, kh0, kh1);
            mma_bf16(s0, ql0, ql2, ql1, ql3, kh0, kh1);
            mma_bf16(s0, qh0, qh2, qh1, qh3, kl0, kl1);
            mma_bf16(s1, qh0, qh2, qh1, qh3, kh2, kh3);
            mma_bf16(s1, ql0, ql2, ql1, ql3, kh2, kh3);
            mma_bf16(s1, qh0, qh2, qh1, qh3, kl2, kl3);

            float mA = fmaxf(fmaxf(s0[0], s0[1]), fmaxf(s1[0], s1[1]));
            float mB = fmaxf(fmaxf(s0[2], s0[3]), fmaxf(s1[2], s1[3]));
            mA = fmaxf(mA, __shfl_xor_sync(0xffffffffu, mA, 1));
            mA = fmaxf(mA, __shfl_xor_sync(0xffffffffu, mA, 2));
            mB = fmaxf(mB, __shfl_xor_sync(0xffffffffu, mB, 1));
            mB = fmaxf(mB, __shfl_xor_sync(0xffffffffu, mB, 2));
            s0[0] = __expf(s0[0] - mA);
            s0[1] = __expf(s0[1] - mA);
            s1[0] = __expf(s1[0] - mA);
            s1[1] = __expf(s1[1] - mA);
            s0[2] = __expf(s0[2] - mB);
            s0[3] = __expf(s0[3] - mB);
            s1[2] = __expf(s1[2] - mB);
            s1[3] = __expf(s1[3] - mB);
            float suA = s0[0] + s0[1] + s1[0] + s1[1];
            float suB = s0[2] + s0[3] + s1[2] + s1[3];
            suA += __shfl_xor_sync(0xffffffffu, suA, 1);
            suA += __shfl_xor_sync(0xffffffffu, suA, 2);
            suB += __shfl_xor_sync(0xffffffffu, suB, 1);
            suB += __shfl_xor_sync(0xffffffffu, suB, 2);
            float ivA = 1.0f / suA;
            float ivB = 1.0f / suB;

            uint32_t pl0, pl1, pl2, pl3;
            uint32_t ph0 = split2(s0[0], s0[1], pl0);
            uint32_t ph1 = split2(s0[2], s0[3], pl1);
            uint32_t ph2 = split2(s1[0], s1[1], pl2);
            uint32_t ph3 = split2(s1[2], s1[3], pl3);

            const float* Vb = sm + OFF_V + (hh * 16 + g) * LD + r0;
            float2 v0 = *(const float2*)(Vb + 2 * t);
            float2 v1 = *(const float2*)(Vb + 2 * t + 8);
            float2 v2 = *(const float2*)(Vb + 8 * LD + 2 * t);
            float2 v3 = *(const float2*)(Vb + 8 * LD + 2 * t + 8);
            uint32_t vl0, vl1, vl2, vl3;
            uint32_t vh0 = split2(v0.x, v0.y, vl0);
            uint32_t vh1 = split2(v1.x, v1.y, vl1);
            uint32_t vh2 = split2(v2.x, v2.y, vl2);
            uint32_t vh3 = split2(v3.x, v3.y, vl3);

            float o0[4] = {0.0f, 0.0f, 0.0f, 0.0f};
            float o1[4] = {0.0f, 0.0f, 0.0f, 0.0f};
            mma_bf16(o0, ph0, ph1, ph2, ph3, vh0, vh1);
            mma_bf16(o0, pl0, pl1, pl2, pl3, vh0, vh1);
            mma_bf16(o0, ph0, ph1, ph2, ph3, vl0, vl1);
            mma_bf16(o1, ph0, ph1, ph2, ph3, vh2, vh3);
            mma_bf16(o1, pl0, pl1, pl2, pl3, vh2, vh3);
            mma_bf16(o1, ph0, ph1, ph2, ph3, vl2, vl3);

            o0[0] *= ivA; o0[1] *= ivA; o1[0] *= ivA; o1[1] *= ivA;
            o0[2] *= ivB; o0[3] *= ivB; o1[2] *= ivB; o1[3] *= ivB;

            // chain: O C-frag == proj A-frag at ks = hh
            uint32_t al0, al1, al2, al3;
            uint32_t ahx0 = split2(o0[0], o0[1], al0);   // (g,   k2t)
            uint32_t ahx1 = split2(o0[2], o0[3], al1);   // (g+8, k2t)
            uint32_t ahx2 = split2(o1[0], o1[1], al2);   // (g,   k2t+8)
            uint32_t ahx3 = split2(o1[2], o1[3], al3);   // (g+8, k2t+8)
#pragma unroll
            for (int j = 0; j < 8; j++) {
                uint4 b = g_fproj[j * 128 + hh * 32 + g * 4 + t];
                mma_bf16(cacc[j], ahx0, ahx1, ahx2, ahx3, b.x, b.y);
                mma_bf16(cacc[j], al0,  al1,  al2,  al3,  b.x, b.y);
                mma_bf16(cacc[j], ahx0, ahx1, ahx2, ahx3, b.z, b.w);
            }
        }
        // all Q/K/V reads done before overwriting Q/K with partials
        __syncthreads();
        float* buf = sm + ((warp & 1) ? OFF_K : OFF_Q);
#pragma unroll
        for (int j = 0; j < 8; j++) {
            int c = 8 * j + 2 * t;
            *(float2*)(buf + (r0 + g) * LD + c)     = make_float2(cacc[j][0], cacc[j][1]);
            *(float2*)(buf + (r0 + g + 8) * LD + c) = make_float2(cacc[j][2], cacc[j][3]);
        }
    }
    __syncthreads();

    // ---- phase 3: LN1 ('a' = bufA+bufB) + residual in place + split x1 ----
    {
        int row = tid >> 2;
        int sub = tid & 3;
        const float* pa = sm + OFF_Q + row * LD + sub * 16;
        const float* pb = sm + OFF_K + row * LD + sub * 16;
        float av[16];
        float s = 0.0f;
#pragma unroll
        for (int c = 0; c < 16; c++) {
            av[c] = pa[c] + pb[c];
            s += av[c];
        }
        s += __shfl_xor_sync(0xffffffffu, s, 1);
        s += __shfl_xor_sync(0xffffffffu, s, 2);
        float mean = s * (1.0f / 64.0f);
        float vv = 0.0f;
#pragma unroll
        for (int c = 0; c < 16; c++) {
            float d2 = av[c] - mean;
            vv += d2 * d2;
        }
        vv += __shfl_xor_sync(0xffffffffu, vv, 1);
        vv += __shfl_xor_sync(0xffffffffu, vv, 2);
        float rstd = rsqrtf(vv * (1.0f / 64.0f) + 1e-5f);
        float* xr = sm + OFF_X + row * LD + sub * 16;
        const float* gg = s_n1g + sub * 16;
        const float* bbv = s_n1b + sub * 16;
        uint32_t* xh = smu + OFF_XH + row * 36 + sub * 8;
        uint32_t* xl = smu + OFF_XL + row * 36 + sub * 8;
#pragma unroll
        for (int c2 = 0; c2 < 8; c2++) {
            float u0 = xr[2 * c2]     + (av[2 * c2]     - mean) * rstd * gg[2 * c2]     + bbv[2 * c2];
            float u1 = xr[2 * c2 + 1] + (av[2 * c2 + 1] - mean) * rstd * gg[2 * c2 + 1] + bbv[2 * c2 + 1];
            xr[2 * c2] = u0;
            xr[2 * c2 + 1] = u1;
            uint32_t lo;
            xh[c2] = split2(u0, u1, lo);
            xl[c2] = lo;
        }
    }
    __syncthreads();

    // ---- phase 4: MLP in two 128-wide halves ----
    float dacc[4][4];
#pragma unroll
    for (int j = 0; j < 4; j++)
#pragma unroll
        for (int i = 0; i < 4; i++) dacc[j][i] = 0.0f;

#pragma unroll 1
    for (int kh = 0; kh < 2; kh++) {
        {
            float d[2][4][4];
#pragma unroll
            for (int i2 = 0; i2 < 2; i2++)
#pragma unroll
                for (int j = 0; j < 4; j++)
#pragma unroll
                    for (int i = 0; i < 4; i++) d[i2][j][i] = 0.0f;
            gemm2_splitA<4, 4>(smu + OFF_XH, smu + OFF_XL, mrow2, g_ffc1, 4, 0,
                               kh * 16 + nh4 * 4, d, g, t);
#pragma unroll
            for (int j = 0; j < 4; j++) {
                int c = nh4 * 32 + 8 * j + 2 * t;
                float b0 = s_fc1b[kh * 128 + c];
                float b1 = s_fc1b[kh * 128 + c + 1];
                int col2 = nh4 * 16 + 4 * j + t;
#pragma unroll
                for (int i2 = 0; i2 < 2; i2++) {
                    float v0 = d[i2][j][0] + b0;
                    float v1 = d[i2][j][1] + b1;
                    float v2 = d[i2][j][2] + b0;
                    float v3 = d[i2][j][3] + b1;
                    v0 = v0 * 0.5f * (1.0f + erff(v0 * 0.70710678118654752f));
                    v1 = v1 * 0.5f * (1.0f + erff(v1 * 0.70710678118654752f));
                    v2 = v2 * 0.5f * (1.0f + erff(v2 * 0.70710678118654752f));
                    v3 = v3 * 0.5f * (1.0f + erff(v3 * 0.70710678118654752f));
                    int r = mrow2 + i2 * 16 + g;
                    uint32_t lo0, lo1;
                    uint32_t hi0 = split2(v0, v1, lo0);
                    uint32_t hi1 = split2(v2, v3, lo1);
                    smu[OFF_HH + r * LDH2 + col2]       = hi0;
                    smu[OFF_HL + r * LDH2 + col2]       = lo0;
                    smu[OFF_HH + (r + 8) * LDH2 + col2] = hi1;
                    smu[OFF_HL + (r + 8) * LDH2 + col2] = lo1;
                }
            }
        }
        __syncthreads();
        gemm1_splitA<4, 8>(smu + OFF_HH, smu + OFF_HL, LDH2, mrow1,
                           g_ffc2, 16, kh * 8, nh1 * 4, dacc, g, t);
        __syncthreads();
    }

    // h2 -> V region (Vt dead)
#pragma unroll
    for (int j = 0; j < 4; j++) {
        int c = nh1 * 32 + 8 * j + 2 * t;
        float b0 = s_fc2b[c];
        float b1 = s_fc2b[c + 1];
        *(float2*)(sm + OFF_V + (mrow1 + g) * LD + c)     = make_float2(dacc[j][0] + b0, dacc[j][1] + b1);
        *(float2*)(sm + OFF_V + (mrow1 + g + 8) * LD + c) = make_float2(dacc[j][2] + b0, dacc[j][3] + b1);
    }
    __syncthreads();

    // ---- phase 5: LN2 fused with final residual + store ----
    {
        int row = tid >> 2;
        int pp = tid & 3;
        const float* h2 = sm + OFF_V + row * LD + pp * 16;
        float s = 0.0f;
#pragma unroll
        for (int c = 0; c < 16; c++) s += h2[c];
        s += __shfl_xor_sync(0xffffffffu, s, 1);
        s += __shfl_xor_sync(0xffffffffu, s, 2);
        float mean = s * (1.0f / 64.0f);
        float vv = 0.0f;
#pragma unroll
        for (int c = 0; c < 16; c++) {
            float d2 = h2[c] - mean;
            vv += d2 * d2;
        }
        vv += __shfl_xor_sync(0xffffffffu, vv, 1);
        vv += __shfl_xor_sync(0xffffffffu, vv, 2);
        float rstd = rsqrtf(vv * (1.0f / 64.0f) + 1e-5f);

        int gbase = token_gaddr(blockIdx.x, row);
#pragma unroll
        for (int q = 0; q < 4; q++) {
            int c = pp * 16 + q * 4;
            float4 xv = *(const float4*)(sm + OFF_X + row * LD + c);
            float4 hv = *(const float4*)(sm + OFF_V + row * LD + c);
            float4 ov;
            ov.x = xv.x + (hv.x - mean) * rstd * s_n2g[c]     + s_n2b[c];
            ov.y = xv.y + (hv.y - mean) * rstd * s_n2g[c + 1] + s_n2b[c + 1];
            ov.z = xv.z + (hv.z - mean) * rstd * s_n2g[c + 2] + s_n2b[c + 2];
            ov.w = xv.w + (hv.w - mean) * rstd * s_n2g[c + 3] + s_n2b[c + 3];
            *(float4*)(out + gbase + c) = ov;
        }
    }
}

// ---------------------------------------------------------------------------
extern "C" void kernel_launch(void* const* d_in, const int* in_sizes, int n_in,
                              void* d_out, int out_size) {
    const float* x      = (const float*)d_in[0];
    const float* qkv_w  = (const float*)d_in[1];
    const float* qkv_b  = (const float*)d_in[2];
    const float* proj_w = (const float*)d_in[3];
    const float* proj_b = (const float*)d_in[4];
    const float* lscale = (const float*)d_in[5];
    const float* cpb_w1 = (const float*)d_in[6];
    const float* cpb_b1 = (const float*)d_in[7];
    const float* cpb_w2 = (const float*)d_in[8];
    const float* n1g    = (const float*)d_in[9];
    const float* n1b    = (const float*)d_in[10];
    const float* n2g    = (const float*)d_in[11];
    const float* n2b    = (const float*)d_in[12];
    const float* fc1_w  = (const float*)d_in[13];
    const float* fc1_b  = (const float*)d_in[14];
    const float* fc2_w  = (const float*)d_in[15];
    const float* fc2_b  = (const float*)d_in[16];
    float* out = (float*)d_out;

    cudaFuncSetAttribute(swin_kernel, cudaFuncAttributeMaxDynamicSharedMemorySize, SMEM_BYTES);

    cpb_kernel<<<196, 128>>>(cpb_w1, cpb_b1, cpb_w2);
    expand_kernel<<<4, 256>>>(lscale);
    wsplit_kernel<<<48, 256>>>(qkv_w, proj_w, fc1_w, fc2_w);
    swin_kernel<<<8192, NTHREADS, SMEM_BYTES>>>(x, qkv_b, proj_b,
                                                n1g, n1b, n2g, n2b,
                                                fc1_b, fc2_b, out);
}